// round 6
// baseline (speedup 1.0000x reference)
#include <cuda_runtime.h>
#include <cuda_bf16.h>

#define NNODES 8192
#define NF 1024
#define NH 512
#define NZ 32

// ---- scratch (device globals; no allocation allowed) ----
__device__ __nv_bfloat162 g_xw0h[NNODES * NH / 2]; // x @ W0 (bf16 pairs)
__device__ float g_h[NNODES * NH];                 // relu(spmm + b0) fp32
__device__ float g_hw[NNODES * 64];                // h @ [W1|W2] fp32
__device__ float g_z[NNODES * 64];                 // [mu | logvar] fp32
__device__ int   g_rowptr[NNODES + 1];

__device__ __forceinline__ unsigned f2tf(float f) {
    unsigned u;
    asm("cvt.rna.tf32.f32 %0, %1;" : "=r"(u) : "f"(f));
    return u;
}

__device__ __forceinline__ void mma_tf32(float c[4], const unsigned a[4],
                                         const unsigned b[2]) {
    asm volatile(
        "mma.sync.aligned.m16n8k8.row.col.f32.tf32.tf32.f32 "
        "{%0,%1,%2,%3}, {%4,%5,%6,%7}, {%8,%9}, {%0,%1,%2,%3};"
        : "+f"(c[0]), "+f"(c[1]), "+f"(c[2]), "+f"(c[3])
        : "r"(a[0]), "r"(a[1]), "r"(a[2]), "r"(a[3]), "r"(b[0]), "r"(b[1]));
}

__device__ __forceinline__ void cpa16(void* s, const void* g) {
    unsigned sa = (unsigned)__cvta_generic_to_shared(s);
    asm volatile("cp.async.cg.shared.global [%0], [%1], 16;" :: "r"(sa), "l"(g));
}
__device__ __forceinline__ void cpa_commit() {
    asm volatile("cp.async.commit_group;");
}

__device__ __forceinline__ float fast_sigmoid(float x) {
    float th;
    asm("tanh.approx.f32 %0, %1;" : "=f"(th) : "f"(0.5f * x));
    return fmaf(0.5f, th, 0.5f);
}

// ---------------------------------------------------------------------------
// CSR row pointers (binary search on sorted rows).
// ---------------------------------------------------------------------------
__global__ void k_rowptr(const int* __restrict__ rows, int E) {
    int r = blockIdx.x * blockDim.x + threadIdx.x;
    if (r > NNODES) return;
    int lo = 0, hi = E;
    while (lo < hi) {
        int mid = (lo + hi) >> 1;
        if (rows[mid] < r) lo = mid + 1; else hi = mid;
    }
    g_rowptr[r] = lo;
}

// ---------------------------------------------------------------------------
// GEMM1 (tf32 mma, 3-stage cp.async): x[8192,1024] @ W0[1024,512] -> bf16.
// 128x64 tile, BK=16, 8 warps (4M x 2N), warp tile 32x32. One sync per kt.
// RNA tf32 conversion applied on fragments (unbiased, no pre-pass).
// As [m][k] stride 20 (bank 4g+t), Bs [k][n] stride 72 (bank 8t+g).
// ---------------------------------------------------------------------------
__global__ __launch_bounds__(256) void k_gemm1(const float* __restrict__ A,
                                               const float* __restrict__ B) {
    __shared__ float As[3][128][20];
    __shared__ float Bs[3][16][72];
    int tid = threadIdx.x, lane = tid & 31, wid = tid >> 5;
    int g = lane >> 2, t = lane & 3;
    int bm = blockIdx.y * 128, bn = blockIdx.x * 64;
    int wm = (wid & 3) * 32, wn = (wid >> 2) * 32;

    float acc[2][4][4];
#pragma unroll
    for (int mi = 0; mi < 2; mi++)
#pragma unroll
        for (int ni = 0; ni < 4; ni++)
#pragma unroll
            for (int j = 0; j < 4; j++) acc[mi][ni][j] = 0.f;

    // load indices: A 128x16 = 512 float4 (2/thread); B 16x64 = 256 float4 (1/thread)
    int a_row[2], a_c4[2];
#pragma unroll
    for (int l = 0; l < 2; l++) {
        int idx = tid * 2 + l;
        a_row[l] = idx >> 2;  a_c4[l] = (idx & 3) * 4;
    }
    int b_row = tid >> 4, b_c4 = (tid & 15) * 4;

    // prologue: stages 0,1
#pragma unroll
    for (int s = 0; s < 2; s++) {
        int k0 = s * 16;
#pragma unroll
        for (int l = 0; l < 2; l++)
            cpa16(&As[s][a_row[l]][a_c4[l]],
                  &A[(size_t)(bm + a_row[l]) * NF + k0 + a_c4[l]]);
        cpa16(&Bs[s][b_row][b_c4], &B[(size_t)(k0 + b_row) * NH + bn + b_c4]);
        cpa_commit();
    }

    const int NKT = NF / 16;   // 64
    for (int kt = 0; kt < NKT; kt++) {
        int st = kt % 3;
        if (kt == NKT - 1) asm volatile("cp.async.wait_group 0;");
        else               asm volatile("cp.async.wait_group 1;");
        __syncthreads();
        if (kt + 2 < NKT) {
            int ns = (kt + 2) % 3, k0 = (kt + 2) * 16;
#pragma unroll
            for (int l = 0; l < 2; l++)
                cpa16(&As[ns][a_row[l]][a_c4[l]],
                      &A[(size_t)(bm + a_row[l]) * NF + k0 + a_c4[l]]);
            cpa16(&Bs[ns][b_row][b_c4], &B[(size_t)(k0 + b_row) * NH + bn + b_c4]);
            cpa_commit();
        }
#pragma unroll
        for (int ks = 0; ks < 16; ks += 8) {
            unsigned af[2][4], bf[4][2];
#pragma unroll
            for (int mi = 0; mi < 2; mi++) {
                int m0 = wm + mi * 16;
                af[mi][0] = f2tf(As[st][m0 + g][ks + t]);
                af[mi][1] = f2tf(As[st][m0 + g + 8][ks + t]);
                af[mi][2] = f2tf(As[st][m0 + g][ks + t + 4]);
                af[mi][3] = f2tf(As[st][m0 + g + 8][ks + t + 4]);
            }
#pragma unroll
            for (int ni = 0; ni < 4; ni++) {
                int n0 = wn + ni * 8;
                bf[ni][0] = f2tf(Bs[st][ks + t][n0 + g]);
                bf[ni][1] = f2tf(Bs[st][ks + t + 4][n0 + g]);
            }
#pragma unroll
            for (int mi = 0; mi < 2; mi++)
#pragma unroll
                for (int ni = 0; ni < 4; ni++)
                    mma_tf32(acc[mi][ni], af[mi], bf[ni]);
        }
    }
#pragma unroll
    for (int mi = 0; mi < 2; mi++)
#pragma unroll
        for (int ni = 0; ni < 4; ni++) {
            int row = bm + wm + mi * 16 + g;
            int col = bn + wn + ni * 8 + 2 * t;
            g_xw0h[((size_t)row * NH + col) >> 1] =
                __float22bfloat162_rn(make_float2(acc[mi][ni][0], acc[mi][ni][1]));
            g_xw0h[((size_t)(row + 8) * NH + col) >> 1] =
                __float22bfloat162_rn(make_float2(acc[mi][ni][2], acc[mi][ni][3]));
        }
}

// ---------------------------------------------------------------------------
// SpMM1: g_h[r,:] = relu(sum vals*xw0[cols,:] + b0). bf16x2 gather, fp32 acc.
// ---------------------------------------------------------------------------
__global__ __launch_bounds__(256) void k_spmm1(const float* __restrict__ vals,
                                               const int* __restrict__ cols,
                                               const float* __restrict__ bias) {
    int r = blockIdx.x;
    int t = threadIdx.x;
    int s = g_rowptr[r], e = g_rowptr[r + 1];
    float2 a0 = {0, 0}, a1 = {0, 0}, a2 = {0, 0}, a3 = {0, 0};
    int i = s;
    for (; i + 4 <= e; i += 4) {
        float v0 = vals[i], v1 = vals[i + 1], v2 = vals[i + 2], v3 = vals[i + 3];
        int   j0 = cols[i], j1 = cols[i + 1], j2 = cols[i + 2], j3 = cols[i + 3];
        float2 f0 = __bfloat1622float2(g_xw0h[(size_t)j0 * 256 + t]);
        float2 f1 = __bfloat1622float2(g_xw0h[(size_t)j1 * 256 + t]);
        float2 f2 = __bfloat1622float2(g_xw0h[(size_t)j2 * 256 + t]);
        float2 f3 = __bfloat1622float2(g_xw0h[(size_t)j3 * 256 + t]);
        a0.x += v0 * f0.x; a0.y += v0 * f0.y;
        a1.x += v1 * f1.x; a1.y += v1 * f1.y;
        a2.x += v2 * f2.x; a2.y += v2 * f2.y;
        a3.x += v3 * f3.x; a3.y += v3 * f3.y;
    }
    for (; i < e; i++) {
        float v = vals[i];
        float2 f = __bfloat1622float2(g_xw0h[(size_t)cols[i] * 256 + t]);
        a0.x += v * f.x; a0.y += v * f.y;
    }
    float h0 = (a0.x + a1.x) + (a2.x + a3.x) + bias[2 * t];
    float h1 = (a0.y + a1.y) + (a2.y + a3.y) + bias[2 * t + 1];
    *(float2*)&g_h[(size_t)r * NH + 2 * t] =
        make_float2(fmaxf(h0, 0.f), fmaxf(h1, 0.f));
}

// ---------------------------------------------------------------------------
// GEMM2 (tf32 mma): g_hw = g_h[8192,512] @ [W1|W2][512,64].
// BM=32 -> grid 256. BK=32, 8 warps (2M x 4N), warp tile 16x16. RNA at fill.
// ---------------------------------------------------------------------------
__global__ __launch_bounds__(256) void k_gemm2(const float* __restrict__ W1,
                                               const float* __restrict__ W2) {
    __shared__ unsigned As[32][40];
    __shared__ unsigned Bs[32][72];
    int tid = threadIdx.x, lane = tid & 31, wid = tid >> 5;
    int g = lane >> 2, t = lane & 3;
    int bm = blockIdx.x * 32;
    int wm = (wid & 1) * 16, wn = (wid >> 1) * 16;

    float acc[2][4];
#pragma unroll
    for (int ni = 0; ni < 2; ni++)
#pragma unroll
        for (int j = 0; j < 4; j++) acc[ni][j] = 0.f;

    for (int k0 = 0; k0 < NH; k0 += 32) {
        {
            int row = tid >> 3, c4 = (tid & 7) * 4;
            float4 v = *(const float4*)&g_h[(size_t)(bm + row) * NH + k0 + c4];
            As[c4 + 0][row] = f2tf(v.x); As[c4 + 1][row] = f2tf(v.y);
            As[c4 + 2][row] = f2tf(v.z); As[c4 + 3][row] = f2tf(v.w);
        }
#pragma unroll
        for (int l = 0; l < 2; l++) {
            int idx = tid * 2 + l;
            int row = idx >> 4, c4 = (idx & 15) * 4;
            float4 w = (c4 < 32)
                ? *(const float4*)&W1[(size_t)(k0 + row) * NZ + c4]
                : *(const float4*)&W2[(size_t)(k0 + row) * NZ + (c4 - 32)];
            Bs[row][c4 + 0] = f2tf(w.x); Bs[row][c4 + 1] = f2tf(w.y);
            Bs[row][c4 + 2] = f2tf(w.z); Bs[row][c4 + 3] = f2tf(w.w);
        }
        __syncthreads();
#pragma unroll
        for (int ks = 0; ks < 32; ks += 8) {
            unsigned af[4], bf[2][2];
            af[0] = As[ks + t][wm + g];
            af[1] = As[ks + t][wm + g + 8];
            af[2] = As[ks + t + 4][wm + g];
            af[3] = As[ks + t + 4][wm + g + 8];
#pragma unroll
            for (int ni = 0; ni < 2; ni++) {
                int n0 = wn + ni * 8;
                bf[ni][0] = Bs[ks + t][n0 + g];
                bf[ni][1] = Bs[ks + t + 4][n0 + g];
            }
#pragma unroll
            for (int ni = 0; ni < 2; ni++)
                mma_tf32(acc[ni], af, bf[ni]);
        }
        __syncthreads();
    }
#pragma unroll
    for (int ni = 0; ni < 2; ni++) {
        int row = bm + wm + g;
        int col = wn + ni * 8 + 2 * t;
        *(float2*)&g_hw[(size_t)row * 64 + col] = make_float2(acc[ni][0], acc[ni][1]);
        *(float2*)&g_hw[(size_t)(row + 8) * 64 + col] = make_float2(acc[ni][2], acc[ni][3]);
    }
}

// ---------------------------------------------------------------------------
// SpMM2: mu/logvar = relu(spmm(g_hw) + bias); writes z/mu/logvar + g_z.
// ---------------------------------------------------------------------------
__global__ __launch_bounds__(256) void k_spmm2(const float* __restrict__ vals,
                                               const int* __restrict__ cols,
                                               const float* __restrict__ b1,
                                               const float* __restrict__ b2,
                                               float* __restrict__ out) {
    int tx = threadIdx.x;                        // 0..63
    int r = blockIdx.x * 4 + threadIdx.y;
    int s = g_rowptr[r], e = g_rowptr[r + 1];
    float a0 = 0, a1 = 0, a2 = 0, a3 = 0;
    int i = s;
    for (; i + 4 <= e; i += 4) {
        float v0 = vals[i], v1 = vals[i + 1], v2 = vals[i + 2], v3 = vals[i + 3];
        int   j0 = cols[i], j1 = cols[i + 1], j2 = cols[i + 2], j3 = cols[i + 3];
        a0 += v0 * g_hw[(size_t)j0 * 64 + tx];
        a1 += v1 * g_hw[(size_t)j1 * 64 + tx];
        a2 += v2 * g_hw[(size_t)j2 * 64 + tx];
        a3 += v3 * g_hw[(size_t)j3 * 64 + tx];
    }
    for (; i < e; i++) {
        a0 += vals[i] * g_hw[(size_t)cols[i] * 64 + tx];
    }
    float bias = (tx < 32) ? b1[tx] : b2[tx - 32];
    float v = fmaxf((a0 + a1) + (a2 + a3) + bias, 0.f);
    g_z[(size_t)r * 64 + tx] = v;

    size_t base = (size_t)NNODES * NNODES;       // after adj_recon
    if (tx < 32) {
        out[base + (size_t)r * NZ + tx] = v;                       // z
        out[base + (size_t)NNODES * NZ + (size_t)r * NZ + tx] = v; // mu
    } else {
        out[base + (size_t)NNODES * NZ * 2 + (size_t)r * NZ + (tx - 32)] = v; // logvar
    }
}

// ---------------------------------------------------------------------------
// Decoder (tf32 mma): adj_recon = sigmoid(z @ z^T). 128x128 tile, K=32.
// 8 warps (4M x 2N), warp tile 32x64. RNA fill; sigmoid via tanh.approx.
// ---------------------------------------------------------------------------
__global__ __launch_bounds__(256) void k_decoder(float* __restrict__ out) {
    __shared__ unsigned zA[32][136];
    __shared__ unsigned zB[32][136];
    int tid = threadIdx.x, lane = tid & 31, wid = tid >> 5;
    int g = lane >> 2, t = lane & 3;
    int i0 = blockIdx.y * 128, j0 = blockIdx.x * 128;
    int wm = (wid & 3) * 32, wn = (wid >> 2) * 64;

#pragma unroll
    for (int l = 0; l < 4; l++) {
        int idx = tid * 4 + l;
        int row = idx >> 3, c4 = (idx & 7) * 4;
        float4 va = *(const float4*)&g_z[(size_t)(i0 + row) * 64 + c4];
        zA[c4 + 0][row] = f2tf(va.x); zA[c4 + 1][row] = f2tf(va.y);
        zA[c4 + 2][row] = f2tf(va.z); zA[c4 + 3][row] = f2tf(va.w);
        float4 vb = *(const float4*)&g_z[(size_t)(j0 + row) * 64 + c4];
        zB[c4 + 0][row] = f2tf(vb.x); zB[c4 + 1][row] = f2tf(vb.y);
        zB[c4 + 2][row] = f2tf(vb.z); zB[c4 + 3][row] = f2tf(vb.w);
    }
    __syncthreads();

    float acc[2][8][4];
#pragma unroll
    for (int mi = 0; mi < 2; mi++)
#pragma unroll
        for (int ni = 0; ni < 8; ni++)
#pragma unroll
            for (int j = 0; j < 4; j++) acc[mi][ni][j] = 0.f;

#pragma unroll
    for (int ks = 0; ks < NZ; ks += 8) {
        unsigned af[2][4], bf[8][2];
#pragma unroll
        for (int mi = 0; mi < 2; mi++) {
            int m0 = wm + mi * 16;
            af[mi][0] = zA[ks + t][m0 + g];
            af[mi][1] = zA[ks + t][m0 + g + 8];
            af[mi][2] = zA[ks + t + 4][m0 + g];
            af[mi][3] = zA[ks + t + 4][m0 + g + 8];
        }
#pragma unroll
        for (int ni = 0; ni < 8; ni++) {
            int n0 = wn + ni * 8;
            bf[ni][0] = zB[ks + t][n0 + g];
            bf[ni][1] = zB[ks + t + 4][n0 + g];
        }
#pragma unroll
        for (int mi = 0; mi < 2; mi++)
#pragma unroll
            for (int ni = 0; ni < 8; ni++)
                mma_tf32(acc[mi][ni], af[mi], bf[ni]);
    }

#pragma unroll
    for (int mi = 0; mi < 2; mi++)
#pragma unroll
        for (int ni = 0; ni < 8; ni++) {
            int row = i0 + wm + mi * 16 + g;
            int col = j0 + wn + ni * 8 + 2 * t;
            float s0 = fast_sigmoid(acc[mi][ni][0]);
            float s1 = fast_sigmoid(acc[mi][ni][1]);
            float s2 = fast_sigmoid(acc[mi][ni][2]);
            float s3 = fast_sigmoid(acc[mi][ni][3]);
            *(float2*)&out[(size_t)row * NNODES + col]       = make_float2(s0, s1);
            *(float2*)&out[(size_t)(row + 8) * NNODES + col] = make_float2(s2, s3);
        }
}

// ---------------------------------------------------------------------------
extern "C" void kernel_launch(void* const* d_in, const int* in_sizes, int n_in,
                              void* d_out, int out_size) {
    const float* x    = (const float*)d_in[0];
    const float* vals = (const float*)d_in[1];
    const float* W0   = (const float*)d_in[2];
    const float* b0   = (const float*)d_in[3];
    const float* W1   = (const float*)d_in[4];
    const float* b1   = (const float*)d_in[5];
    const float* W2   = (const float*)d_in[6];
    const float* b2   = (const float*)d_in[7];
    const int*   rows = (const int*)d_in[8];
    const int*   cols = (const int*)d_in[9];
    int E = in_sizes[1];
    float* out = (float*)d_out;

    k_rowptr<<<(NNODES + 256) / 256, 256>>>(rows, E);
    k_gemm1<<<dim3(NH / 64, NNODES / 128), 256>>>(x, W0);
    k_spmm1<<<NNODES, 256>>>(vals, cols, b0);
    k_gemm2<<<NNODES / 32, 256>>>(W1, W2);
    k_spmm2<<<NNODES / 4, dim3(64, 4)>>>(vals, cols, b1, b2, out);
    k_decoder<<<dim3(NNODES / 128, NNODES / 128), 256>>>(out);
}

// round 7
// speedup vs baseline: 1.0966x; 1.0966x over previous
#include <cuda_runtime.h>
#include <cuda_bf16.h>

#define NNODES 8192
#define NF 1024
#define NH 512
#define NZ 32

// ---- scratch (device globals; no allocation allowed) ----
__device__ unsigned g_xr[NNODES * NF];             // x rounded to tf32 (RNA)
__device__ unsigned g_w0r[NF * NH];                // W0 rounded to tf32 (RNA)
__device__ __nv_bfloat162 g_xw0h[NNODES * NH / 2]; // x @ W0 (bf16 pairs)
__device__ float g_h[NNODES * NH];                 // relu(spmm + b0) fp32
__device__ float g_hw[NNODES * 64];                // h @ [W1|W2] fp32
__device__ float g_z[NNODES * 64];                 // [mu | logvar] fp32
__device__ int   g_rowptr[NNODES + 1];

__device__ __forceinline__ unsigned f2tf(float f) {
    unsigned u;
    asm("cvt.rna.tf32.f32 %0, %1;" : "=r"(u) : "f"(f));
    return u;
}

__device__ __forceinline__ void mma_tf32(float c[4], const unsigned a[4],
                                         const unsigned b[2]) {
    asm volatile(
        "mma.sync.aligned.m16n8k8.row.col.f32.tf32.tf32.f32 "
        "{%0,%1,%2,%3}, {%4,%5,%6,%7}, {%8,%9}, {%0,%1,%2,%3};"
        : "+f"(c[0]), "+f"(c[1]), "+f"(c[2]), "+f"(c[3])
        : "r"(a[0]), "r"(a[1]), "r"(a[2]), "r"(a[3]), "r"(b[0]), "r"(b[1]));
}

__device__ __forceinline__ void cpa16(void* s, const void* g) {
    unsigned sa = (unsigned)__cvta_generic_to_shared(s);
    asm volatile("cp.async.cg.shared.global [%0], [%1], 16;" :: "r"(sa), "l"(g));
}
__device__ __forceinline__ void cpa_commit() {
    asm volatile("cp.async.commit_group;");
}

__device__ __forceinline__ float fast_sigmoid(float x) {
    float th;
    asm("tanh.approx.f32 %0, %1;" : "=f"(th) : "f"(0.5f * x));
    return fmaf(0.5f, th, 0.5f);
}

// ---------------------------------------------------------------------------
// CSR row pointers (binary search on sorted rows).
// ---------------------------------------------------------------------------
__global__ void k_rowptr(const int* __restrict__ rows, int E) {
    int r = blockIdx.x * blockDim.x + threadIdx.x;
    if (r > NNODES) return;
    int lo = 0, hi = E;
    while (lo < hi) {
        int mid = (lo + hi) >> 1;
        if (rows[mid] < r) lo = mid + 1; else hi = mid;
    }
    g_rowptr[r] = lo;
}

// ---------------------------------------------------------------------------
// Round fp32 -> tf32 bits (RNA). n4 = element count / 4.
// ---------------------------------------------------------------------------
__global__ void k_round(const float* __restrict__ src, unsigned* __restrict__ dst,
                        int n4) {
    int i = blockIdx.x * blockDim.x + threadIdx.x;
    if (i >= n4) return;
    float4 v = ((const float4*)src)[i];
    uint4 o;
    o.x = f2tf(v.x); o.y = f2tf(v.y); o.z = f2tf(v.z); o.w = f2tf(v.w);
    ((uint4*)dst)[i] = o;
}

// ---------------------------------------------------------------------------
// GEMM1 (tf32 mma, 3-stage cp.async, 512 thr): xr[8192,1024] @ w0r[1024,512].
// BM=BN=128, BK=16, 16 warps (4M x 4N), warp tile 32x32, 1 sync per kt.
// As [m][k] stride 20 (bank 20g+t), Bs [k][n] stride 136 (bank 8t+g).
// Dynamic smem: 3*(128*20 + 16*136)*4 = 56832 B.
// ---------------------------------------------------------------------------
__global__ __launch_bounds__(512, 2) void k_gemm1() {
    extern __shared__ unsigned dsm[];
    unsigned (*As)[128][20] = (unsigned (*)[128][20])dsm;
    unsigned (*Bs)[16][136] = (unsigned (*)[16][136])(dsm + 3 * 128 * 20);

    int tid = threadIdx.x, lane = tid & 31, wid = tid >> 5;
    int g = lane >> 2, t = lane & 3;
    int bm = blockIdx.y * 128, bn = blockIdx.x * 128;
    int wm = (wid & 3) * 32, wn = (wid >> 2) * 32;

    float acc[2][4][4];
#pragma unroll
    for (int mi = 0; mi < 2; mi++)
#pragma unroll
        for (int ni = 0; ni < 4; ni++)
#pragma unroll
            for (int j = 0; j < 4; j++) acc[mi][ni][j] = 0.f;

    // per-thread load slots: A 128x16=512 f4 (1/thread), B 16x128=512 f4 (1/thread)
    int a_row = tid >> 2, a_c4 = (tid & 3) * 4;
    int b_row = tid >> 5, b_c4 = (tid & 31) * 4;

    // prologue: stages 0,1
#pragma unroll
    for (int s = 0; s < 2; s++) {
        int k0 = s * 16;
        cpa16(&As[s][a_row][a_c4], &g_xr[(size_t)(bm + a_row) * NF + k0 + a_c4]);
        cpa16(&Bs[s][b_row][b_c4], &g_w0r[(size_t)(k0 + b_row) * NH + bn + b_c4]);
        cpa_commit();
    }

    const int NKT = NF / 16;   // 64
    for (int kt = 0; kt < NKT; kt++) {
        int st = kt % 3;
        if (kt == NKT - 1) asm volatile("cp.async.wait_group 0;");
        else               asm volatile("cp.async.wait_group 1;");
        __syncthreads();
        if (kt + 2 < NKT) {
            int ns = (kt + 2) % 3, k0 = (kt + 2) * 16;
            cpa16(&As[ns][a_row][a_c4], &g_xr[(size_t)(bm + a_row) * NF + k0 + a_c4]);
            cpa16(&Bs[ns][b_row][b_c4], &g_w0r[(size_t)(k0 + b_row) * NH + bn + b_c4]);
            cpa_commit();
        }
#pragma unroll
        for (int ks = 0; ks < 16; ks += 8) {
            unsigned af[2][4], bf[4][2];
#pragma unroll
            for (int mi = 0; mi < 2; mi++) {
                int m0 = wm + mi * 16;
                af[mi][0] = As[st][m0 + g][ks + t];
                af[mi][1] = As[st][m0 + g + 8][ks + t];
                af[mi][2] = As[st][m0 + g][ks + t + 4];
                af[mi][3] = As[st][m0 + g + 8][ks + t + 4];
            }
#pragma unroll
            for (int ni = 0; ni < 4; ni++) {
                int n0 = wn + ni * 8;
                bf[ni][0] = Bs[st][ks + t][n0 + g];
                bf[ni][1] = Bs[st][ks + t + 4][n0 + g];
            }
#pragma unroll
            for (int mi = 0; mi < 2; mi++)
#pragma unroll
                for (int ni = 0; ni < 4; ni++)
                    mma_tf32(acc[mi][ni], af[mi], bf[ni]);
        }
    }
#pragma unroll
    for (int mi = 0; mi < 2; mi++)
#pragma unroll
        for (int ni = 0; ni < 4; ni++) {
            int row = bm + wm + mi * 16 + g;
            int col = bn + wn + ni * 8 + 2 * t;
            g_xw0h[((size_t)row * NH + col) >> 1] =
                __float22bfloat162_rn(make_float2(acc[mi][ni][0], acc[mi][ni][1]));
            g_xw0h[((size_t)(row + 8) * NH + col) >> 1] =
                __float22bfloat162_rn(make_float2(acc[mi][ni][2], acc[mi][ni][3]));
        }
}

// ---------------------------------------------------------------------------
// SpMM1: g_h[r,:] = relu(sum vals*xw0[cols,:] + b0). bf16x2 gather, fp32 acc.
// ---------------------------------------------------------------------------
__global__ __launch_bounds__(256) void k_spmm1(const float* __restrict__ vals,
                                               const int* __restrict__ cols,
                                               const float* __restrict__ bias) {
    int r = blockIdx.x;
    int t = threadIdx.x;
    int s = g_rowptr[r], e = g_rowptr[r + 1];
    float2 a0 = {0, 0}, a1 = {0, 0}, a2 = {0, 0}, a3 = {0, 0};
    int i = s;
    for (; i + 4 <= e; i += 4) {
        float v0 = vals[i], v1 = vals[i + 1], v2 = vals[i + 2], v3 = vals[i + 3];
        int   j0 = cols[i], j1 = cols[i + 1], j2 = cols[i + 2], j3 = cols[i + 3];
        float2 f0 = __bfloat1622float2(g_xw0h[(size_t)j0 * 256 + t]);
        float2 f1 = __bfloat1622float2(g_xw0h[(size_t)j1 * 256 + t]);
        float2 f2 = __bfloat1622float2(g_xw0h[(size_t)j2 * 256 + t]);
        float2 f3 = __bfloat1622float2(g_xw0h[(size_t)j3 * 256 + t]);
        a0.x += v0 * f0.x; a0.y += v0 * f0.y;
        a1.x += v1 * f1.x; a1.y += v1 * f1.y;
        a2.x += v2 * f2.x; a2.y += v2 * f2.y;
        a3.x += v3 * f3.x; a3.y += v3 * f3.y;
    }
    for (; i < e; i++) {
        float v = vals[i];
        float2 f = __bfloat1622float2(g_xw0h[(size_t)cols[i] * 256 + t]);
        a0.x += v * f.x; a0.y += v * f.y;
    }
    float h0 = (a0.x + a1.x) + (a2.x + a3.x) + bias[2 * t];
    float h1 = (a0.y + a1.y) + (a2.y + a3.y) + bias[2 * t + 1];
    *(float2*)&g_h[(size_t)r * NH + 2 * t] =
        make_float2(fmaxf(h0, 0.f), fmaxf(h1, 0.f));
}

// ---------------------------------------------------------------------------
// GEMM2 (tf32 mma, 3-stage cp.async): g_hw = g_h[8192,512] @ [W1|W2][512,64].
// BM=32, BK=32, grid 256, 8 warps (2M x 4N), warp tile 16x16.
// As [m][k] stride 36 (bank 4g+t), Bs [k][n] stride 72 (bank 8t+g).
// RNA cvt applied on fragments. Static smem 3*(32*36+32*72)*4 = 41472 B.
// ---------------------------------------------------------------------------
__global__ __launch_bounds__(256) void k_gemm2(const float* __restrict__ W1,
                                               const float* __restrict__ W2) {
    __shared__ float As[3][32][36];
    __shared__ float Bs[3][32][72];
    int tid = threadIdx.x, lane = tid & 31, wid = tid >> 5;
    int g = lane >> 2, t = lane & 3;
    int bm = blockIdx.x * 32;
    int wm = (wid & 1) * 16, wn = (wid >> 1) * 16;

    float acc[2][4];
#pragma unroll
    for (int ni = 0; ni < 2; ni++)
#pragma unroll
        for (int j = 0; j < 4; j++) acc[ni][j] = 0.f;

    // loads: A 32x32 = 256 f4 (1/thread); B 32x64 = 512 f4 (2/thread)
    int a_row = tid >> 3, a_c4 = (tid & 7) * 4;
    int b_row[2], b_c4[2];
#pragma unroll
    for (int l = 0; l < 2; l++) {
        int idx = tid * 2 + l;
        b_row[l] = idx >> 4;  b_c4[l] = (idx & 15) * 4;
    }

#pragma unroll
    for (int s = 0; s < 2; s++) {
        int k0 = s * 32;
        cpa16(&As[s][a_row][a_c4], &g_h[(size_t)(bm + a_row) * NH + k0 + a_c4]);
#pragma unroll
        for (int l = 0; l < 2; l++) {
            const float* src = (b_c4[l] < 32)
                ? &W1[(size_t)(k0 + b_row[l]) * NZ + b_c4[l]]
                : &W2[(size_t)(k0 + b_row[l]) * NZ + (b_c4[l] - 32)];
            cpa16(&Bs[s][b_row[l]][b_c4[l]], src);
        }
        cpa_commit();
    }

    const int NKT = NH / 32;   // 16
    for (int kt = 0; kt < NKT; kt++) {
        int st = kt % 3;
        if (kt == NKT - 1) asm volatile("cp.async.wait_group 0;");
        else               asm volatile("cp.async.wait_group 1;");
        __syncthreads();
        if (kt + 2 < NKT) {
            int ns = (kt + 2) % 3, k0 = (kt + 2) * 32;
            cpa16(&As[ns][a_row][a_c4], &g_h[(size_t)(bm + a_row) * NH + k0 + a_c4]);
#pragma unroll
            for (int l = 0; l < 2; l++) {
                const float* src = (b_c4[l] < 32)
                    ? &W1[(size_t)(k0 + b_row[l]) * NZ + b_c4[l]]
                    : &W2[(size_t)(k0 + b_row[l]) * NZ + (b_c4[l] - 32)];
                cpa16(&Bs[ns][b_row[l]][b_c4[l]], src);
            }
            cpa_commit();
        }
#pragma unroll
        for (int ks = 0; ks < 32; ks += 8) {
            unsigned af[4], bf[2][2];
            af[0] = f2tf(As[st][wm + g][ks + t]);
            af[1] = f2tf(As[st][wm + g + 8][ks + t]);
            af[2] = f2tf(As[st][wm + g][ks + t + 4]);
            af[3] = f2tf(As[st][wm + g + 8][ks + t + 4]);
#pragma unroll
            for (int ni = 0; ni < 2; ni++) {
                int n0 = wn + ni * 8;
                bf[ni][0] = f2tf(Bs[st][ks + t][n0 + g]);
                bf[ni][1] = f2tf(Bs[st][ks + t + 4][n0 + g]);
            }
#pragma unroll
            for (int ni = 0; ni < 2; ni++)
                mma_tf32(acc[ni], af, bf[ni]);
        }
    }
#pragma unroll
    for (int ni = 0; ni < 2; ni++) {
        int row = bm + wm + g;
        int col = wn + ni * 8 + 2 * t;
        *(float2*)&g_hw[(size_t)row * 64 + col] = make_float2(acc[ni][0], acc[ni][1]);
        *(float2*)&g_hw[(size_t)(row + 8) * 64 + col] = make_float2(acc[ni][2], acc[ni][3]);
    }
}

// ---------------------------------------------------------------------------
// SpMM2: mu/logvar = relu(spmm(g_hw) + bias); writes z/mu/logvar + g_z.
// ---------------------------------------------------------------------------
__global__ __launch_bounds__(256) void k_spmm2(const float* __restrict__ vals,
                                               const int* __restrict__ cols,
                                               const float* __restrict__ b1,
                                               const float* __restrict__ b2,
                                               float* __restrict__ out) {
    int tx = threadIdx.x;                        // 0..63
    int r = blockIdx.x * 4 + threadIdx.y;
    int s = g_rowptr[r], e = g_rowptr[r + 1];
    float a0 = 0, a1 = 0, a2 = 0, a3 = 0;
    int i = s;
    for (; i + 4 <= e; i += 4) {
        float v0 = vals[i], v1 = vals[i + 1], v2 = vals[i + 2], v3 = vals[i + 3];
        int   j0 = cols[i], j1 = cols[i + 1], j2 = cols[i + 2], j3 = cols[i + 3];
        a0 += v0 * g_hw[(size_t)j0 * 64 + tx];
        a1 += v1 * g_hw[(size_t)j1 * 64 + tx];
        a2 += v2 * g_hw[(size_t)j2 * 64 + tx];
        a3 += v3 * g_hw[(size_t)j3 * 64 + tx];
    }
    for (; i < e; i++) {
        a0 += vals[i] * g_hw[(size_t)cols[i] * 64 + tx];
    }
    float bias = (tx < 32) ? b1[tx] : b2[tx - 32];
    float v = fmaxf((a0 + a1) + (a2 + a3) + bias, 0.f);
    g_z[(size_t)r * 64 + tx] = v;

    size_t base = (size_t)NNODES * NNODES;       // after adj_recon
    if (tx < 32) {
        out[base + (size_t)r * NZ + tx] = v;                       // z
        out[base + (size_t)NNODES * NZ + (size_t)r * NZ + tx] = v; // mu
    } else {
        out[base + (size_t)NNODES * NZ * 2 + (size_t)r * NZ + (tx - 32)] = v; // logvar
    }
}

// ---------------------------------------------------------------------------
// Decoder (tf32 mma): adj_recon = sigmoid(z @ z^T). 128x128 tile, K=32.
// 8 warps (4M x 2N), warp tile 32x64. RNA fill; sigmoid via tanh.approx.
// ---------------------------------------------------------------------------
__global__ __launch_bounds__(256) void k_decoder(float* __restrict__ out) {
    __shared__ unsigned zA[32][136];
    __shared__ unsigned zB[32][136];
    int tid = threadIdx.x, lane = tid & 31, wid = tid >> 5;
    int g = lane >> 2, t = lane & 3;
    int i0 = blockIdx.y * 128, j0 = blockIdx.x * 128;
    int wm = (wid & 3) * 32, wn = (wid >> 2) * 64;

#pragma unroll
    for (int l = 0; l < 4; l++) {
        int idx = tid * 4 + l;
        int row = idx >> 3, c4 = (idx & 7) * 4;
        float4 va = *(const float4*)&g_z[(size_t)(i0 + row) * 64 + c4];
        zA[c4 + 0][row] = f2tf(va.x); zA[c4 + 1][row] = f2tf(va.y);
        zA[c4 + 2][row] = f2tf(va.z); zA[c4 + 3][row] = f2tf(va.w);
        float4 vb = *(const float4*)&g_z[(size_t)(j0 + row) * 64 + c4];
        zB[c4 + 0][row] = f2tf(vb.x); zB[c4 + 1][row] = f2tf(vb.y);
        zB[c4 + 2][row] = f2tf(vb.z); zB[c4 + 3][row] = f2tf(vb.w);
    }
    __syncthreads();

    float acc[2][8][4];
#pragma unroll
    for (int mi = 0; mi < 2; mi++)
#pragma unroll
        for (int ni = 0; ni < 8; ni++)
#pragma unroll
            for (int j = 0; j < 4; j++) acc[mi][ni][j] = 0.f;

#pragma unroll
    for (int ks = 0; ks < NZ; ks += 8) {
        unsigned af[2][4], bf[8][2];
#pragma unroll
        for (int mi = 0; mi < 2; mi++) {
            int m0 = wm + mi * 16;
            af[mi][0] = zA[ks + t][m0 + g];
            af[mi][1] = zA[ks + t][m0 + g + 8];
            af[mi][2] = zA[ks + t + 4][m0 + g];
            af[mi][3] = zA[ks + t + 4][m0 + g + 8];
        }
#pragma unroll
        for (int ni = 0; ni < 8; ni++) {
            int n0 = wn + ni * 8;
            bf[ni][0] = zB[ks + t][n0 + g];
            bf[ni][1] = zB[ks + t + 4][n0 + g];
        }
#pragma unroll
        for (int mi = 0; mi < 2; mi++)
#pragma unroll
            for (int ni = 0; ni < 8; ni++)
                mma_tf32(acc[mi][ni], af[mi], bf[ni]);
    }

#pragma unroll
    for (int mi = 0; mi < 2; mi++)
#pragma unroll
        for (int ni = 0; ni < 8; ni++) {
            int row = i0 + wm + mi * 16 + g;
            int col = j0 + wn + ni * 8 + 2 * t;
            float s0 = fast_sigmoid(acc[mi][ni][0]);
            float s1 = fast_sigmoid(acc[mi][ni][1]);
            float s2 = fast_sigmoid(acc[mi][ni][2]);
            float s3 = fast_sigmoid(acc[mi][ni][3]);
            *(float2*)&out[(size_t)row * NNODES + col]       = make_float2(s0, s1);
            *(float2*)&out[(size_t)(row + 8) * NNODES + col] = make_float2(s2, s3);
        }
}

// ---------------------------------------------------------------------------
extern "C" void kernel_launch(void* const* d_in, const int* in_sizes, int n_in,
                              void* d_out, int out_size) {
    const float* x    = (const float*)d_in[0];
    const float* vals = (const float*)d_in[1];
    const float* W0   = (const float*)d_in[2];
    const float* b0   = (const float*)d_in[3];
    const float* W1   = (const float*)d_in[4];
    const float* b1   = (const float*)d_in[5];
    const float* W2   = (const float*)d_in[6];
    const float* b2   = (const float*)d_in[7];
    const int*   rows = (const int*)d_in[8];
    const int*   cols = (const int*)d_in[9];
    int E = in_sizes[1];
    float* out = (float*)d_out;

    unsigned* xr  = nullptr;  cudaGetSymbolAddress((void**)&xr,  g_xr);
    unsigned* w0r = nullptr;  cudaGetSymbolAddress((void**)&w0r, g_w0r);

    const int GEMM1_SMEM = 3 * (128 * 20 + 16 * 136) * 4;   // 56832 B
    cudaFuncSetAttribute(k_gemm1, cudaFuncAttributeMaxDynamicSharedMemorySize,
                         GEMM1_SMEM);

    k_rowptr<<<(NNODES + 256) / 256, 256>>>(rows, E);
    k_round<<<(NNODES * NF / 4 + 255) / 256, 256>>>(x, xr, NNODES * NF / 4);
    k_round<<<(NF * NH / 4 + 255) / 256, 256>>>(W0, w0r, NF * NH / 4);
    k_gemm1<<<dim3(NH / 128, NNODES / 128), 512, GEMM1_SMEM>>>();
    k_spmm1<<<NNODES, 256>>>(vals, cols, b0);
    k_gemm2<<<NNODES / 32, 256>>>(W1, W2);
    k_spmm2<<<NNODES / 4, dim3(64, 4)>>>(vals, cols, b1, b2, out);
    k_decoder<<<dim3(NNODES / 128, NNODES / 128), 256>>>(out);
}

// round 8
// speedup vs baseline: 1.2693x; 1.1575x over previous
#include <cuda_runtime.h>
#include <cuda_bf16.h>

#define NNODES 8192
#define NF 1024
#define NH 512
#define NZ 32

// ---- scratch (device globals; no allocation allowed) ----
__device__ __nv_bfloat16 g_xb[NNODES * NF];        // x as bf16 [m][k]
__device__ __nv_bfloat16 g_w0t[NH * NF];           // W0^T as bf16 [n][k]
__device__ __nv_bfloat162 g_xw0h[NNODES * NH / 2]; // x @ W0 (bf16 pairs)
__device__ float g_h[NNODES * NH];                 // relu(spmm + b0) fp32
__device__ float g_hw[NNODES * 64];                // h @ [W1|W2] fp32
__device__ float g_z[NNODES * 64];                 // [mu | logvar] fp32
__device__ int   g_rowptr[NNODES + 1];

__device__ __forceinline__ unsigned f2tf(float f) {
    unsigned u;
    asm("cvt.rna.tf32.f32 %0, %1;" : "=r"(u) : "f"(f));
    return u;
}

__device__ __forceinline__ void mma_tf32(float c[4], const unsigned a[4],
                                         const unsigned b[2]) {
    asm volatile(
        "mma.sync.aligned.m16n8k8.row.col.f32.tf32.tf32.f32 "
        "{%0,%1,%2,%3}, {%4,%5,%6,%7}, {%8,%9}, {%0,%1,%2,%3};"
        : "+f"(c[0]), "+f"(c[1]), "+f"(c[2]), "+f"(c[3])
        : "r"(a[0]), "r"(a[1]), "r"(a[2]), "r"(a[3]), "r"(b[0]), "r"(b[1]));
}

__device__ __forceinline__ void mma_bf16(float c[4], const unsigned a[4],
                                         const unsigned b[2]) {
    asm volatile(
        "mma.sync.aligned.m16n8k16.row.col.f32.bf16.bf16.f32 "
        "{%0,%1,%2,%3}, {%4,%5,%6,%7}, {%8,%9}, {%0,%1,%2,%3};"
        : "+f"(c[0]), "+f"(c[1]), "+f"(c[2]), "+f"(c[3])
        : "r"(a[0]), "r"(a[1]), "r"(a[2]), "r"(a[3]), "r"(b[0]), "r"(b[1]));
}

__device__ __forceinline__ void cpa16(void* s, const void* g) {
    unsigned sa = (unsigned)__cvta_generic_to_shared(s);
    asm volatile("cp.async.cg.shared.global [%0], [%1], 16;" :: "r"(sa), "l"(g));
}
__device__ __forceinline__ void cpa_commit() {
    asm volatile("cp.async.commit_group;");
}

__device__ __forceinline__ float fast_sigmoid(float x) {
    float th;
    asm("tanh.approx.f32 %0, %1;" : "=f"(th) : "f"(0.5f * x));
    return fmaf(0.5f, th, 0.5f);
}

// ---------------------------------------------------------------------------
// CSR row pointers (binary search on sorted rows).
// ---------------------------------------------------------------------------
__global__ void k_rowptr(const int* __restrict__ rows, int E) {
    int r = blockIdx.x * blockDim.x + threadIdx.x;
    if (r > NNODES) return;
    int lo = 0, hi = E;
    while (lo < hi) {
        int mid = (lo + hi) >> 1;
        if (rows[mid] < r) lo = mid + 1; else hi = mid;
    }
    g_rowptr[r] = lo;
}

// ---------------------------------------------------------------------------
// Convert fp32 -> bf16 (RNE). n4 = element count / 4.
// ---------------------------------------------------------------------------
__global__ void k_cvt_bf16(const float* __restrict__ src,
                           __nv_bfloat162* __restrict__ dst, int n4) {
    int i = blockIdx.x * blockDim.x + threadIdx.x;
    if (i >= n4) return;
    float4 v = ((const float4*)src)[i];
    dst[i * 2 + 0] = __float22bfloat162_rn(make_float2(v.x, v.y));
    dst[i * 2 + 1] = __float22bfloat162_rn(make_float2(v.z, v.w));
}

// ---------------------------------------------------------------------------
// W0[1024,512] fp32 -> g_w0t[512,1024] bf16 (tiled transpose via smem).
// grid (NH/32, NF/32), block (32, 8).
// ---------------------------------------------------------------------------
__global__ void k_cvt_w0t(const float* __restrict__ W0) {
    __shared__ float tile[32][33];
    int n0 = blockIdx.x * 32, k0 = blockIdx.y * 32;
#pragma unroll
    for (int i = 0; i < 4; i++) {
        int k = threadIdx.y * 4 + i;           // 0..31
        tile[k][threadIdx.x] = W0[(size_t)(k0 + k) * NH + n0 + threadIdx.x];
    }
    __syncthreads();
#pragma unroll
    for (int i = 0; i < 4; i++) {
        int n = threadIdx.y * 4 + i;
        g_w0t[(size_t)(n0 + n) * NF + k0 + threadIdx.x] =
            __float2bfloat16_rn(tile[threadIdx.x][n]);
    }
}

// ---------------------------------------------------------------------------
// GEMM1 (bf16 mma m16n8k16, 3-stage cp.async, 512 thr):
// g_xw0h = xb[8192,1024] @ w0t^T -> bf16. BM=BN=128, BK=32.
// 16 warps (4M x 4N), warp tile 32x32, 1 sync per kt.
// As/Bs [row][k] bf16, stride 40 bf16 = 80 B (bank (20g+t)%32, conflict-free).
// Dynamic smem: 3 * 2 * 128*40*2 = 61440 B.
// ---------------------------------------------------------------------------
__global__ __launch_bounds__(512, 2) void k_gemm1() {
    extern __shared__ unsigned short dsm[];
    unsigned short (*As)[128][40] = (unsigned short (*)[128][40])dsm;
    unsigned short (*Bs)[128][40] = (unsigned short (*)[128][40])(dsm + 3 * 128 * 40);

    int tid = threadIdx.x, lane = tid & 31, wid = tid >> 5;
    int g = lane >> 2, t = lane & 3;
    int bm = blockIdx.y * 128, bn = blockIdx.x * 128;
    int wm = (wid & 3) * 32, wn = (wid >> 2) * 32;

    float acc[2][4][4];
#pragma unroll
    for (int mi = 0; mi < 2; mi++)
#pragma unroll
        for (int ni = 0; ni < 4; ni++)
#pragma unroll
            for (int j = 0; j < 4; j++) acc[mi][ni][j] = 0.f;

    // loads: tile 128 rows x 32 bf16 = 64 B/row -> 512 x 16B chunks, 1/thread
    int l_row = tid >> 2, l_c8 = (tid & 3) * 8;   // bf16 col offset

#pragma unroll
    for (int s = 0; s < 2; s++) {
        int k0 = s * 32;
        cpa16(&As[s][l_row][l_c8], &g_xb[(size_t)(bm + l_row) * NF + k0 + l_c8]);
        cpa16(&Bs[s][l_row][l_c8], &g_w0t[(size_t)(bn + l_row) * NF + k0 + l_c8]);
        cpa_commit();
    }

    const int NKT = NF / 32;   // 32
    for (int kt = 0; kt < NKT; kt++) {
        int st = kt % 3;
        if (kt == NKT - 1) asm volatile("cp.async.wait_group 0;");
        else               asm volatile("cp.async.wait_group 1;");
        __syncthreads();
        if (kt + 2 < NKT) {
            int ns = (kt + 2) % 3, k0 = (kt + 2) * 32;
            cpa16(&As[ns][l_row][l_c8], &g_xb[(size_t)(bm + l_row) * NF + k0 + l_c8]);
            cpa16(&Bs[ns][l_row][l_c8], &g_w0t[(size_t)(bn + l_row) * NF + k0 + l_c8]);
            cpa_commit();
        }
#pragma unroll
        for (int ks = 0; ks < 32; ks += 16) {
            unsigned af[2][4], bf[4][2];
#pragma unroll
            for (int mi = 0; mi < 2; mi++) {
                int m0 = wm + mi * 16;
                af[mi][0] = *(const unsigned*)&As[st][m0 + g][ks + 2 * t];
                af[mi][1] = *(const unsigned*)&As[st][m0 + g + 8][ks + 2 * t];
                af[mi][2] = *(const unsigned*)&As[st][m0 + g][ks + 2 * t + 8];
                af[mi][3] = *(const unsigned*)&As[st][m0 + g + 8][ks + 2 * t + 8];
            }
#pragma unroll
            for (int ni = 0; ni < 4; ni++) {
                int n0 = wn + ni * 8;
                bf[ni][0] = *(const unsigned*)&Bs[st][n0 + g][ks + 2 * t];
                bf[ni][1] = *(const unsigned*)&Bs[st][n0 + g][ks + 2 * t + 8];
            }
#pragma unroll
            for (int mi = 0; mi < 2; mi++)
#pragma unroll
                for (int ni = 0; ni < 4; ni++)
                    mma_bf16(acc[mi][ni], af[mi], bf[ni]);
        }
    }
#pragma unroll
    for (int mi = 0; mi < 2; mi++)
#pragma unroll
        for (int ni = 0; ni < 4; ni++) {
            int row = bm + wm + mi * 16 + g;
            int col = bn + wn + ni * 8 + 2 * t;
            g_xw0h[((size_t)row * NH + col) >> 1] =
                __float22bfloat162_rn(make_float2(acc[mi][ni][0], acc[mi][ni][1]));
            g_xw0h[((size_t)(row + 8) * NH + col) >> 1] =
                __float22bfloat162_rn(make_float2(acc[mi][ni][2], acc[mi][ni][3]));
        }
}

// ---------------------------------------------------------------------------
// SpMM1: g_h[r,:] = relu(sum vals*xw0[cols,:] + b0). bf16x2 gather, fp32 acc.
// ---------------------------------------------------------------------------
__global__ __launch_bounds__(256) void k_spmm1(const float* __restrict__ vals,
                                               const int* __restrict__ cols,
                                               const float* __restrict__ bias) {
    int r = blockIdx.x;
    int t = threadIdx.x;
    int s = g_rowptr[r], e = g_rowptr[r + 1];
    float2 a0 = {0, 0}, a1 = {0, 0}, a2 = {0, 0}, a3 = {0, 0};
    int i = s;
    for (; i + 4 <= e; i += 4) {
        float v0 = vals[i], v1 = vals[i + 1], v2 = vals[i + 2], v3 = vals[i + 3];
        int   j0 = cols[i], j1 = cols[i + 1], j2 = cols[i + 2], j3 = cols[i + 3];
        float2 f0 = __bfloat1622float2(g_xw0h[(size_t)j0 * 256 + t]);
        float2 f1 = __bfloat1622float2(g_xw0h[(size_t)j1 * 256 + t]);
        float2 f2 = __bfloat1622float2(g_xw0h[(size_t)j2 * 256 + t]);
        float2 f3 = __bfloat1622float2(g_xw0h[(size_t)j3 * 256 + t]);
        a0.x += v0 * f0.x; a0.y += v0 * f0.y;
        a1.x += v1 * f1.x; a1.y += v1 * f1.y;
        a2.x += v2 * f2.x; a2.y += v2 * f2.y;
        a3.x += v3 * f3.x; a3.y += v3 * f3.y;
    }
    for (; i < e; i++) {
        float v = vals[i];
        float2 f = __bfloat1622float2(g_xw0h[(size_t)cols[i] * 256 + t]);
        a0.x += v * f.x; a0.y += v * f.y;
    }
    float h0 = (a0.x + a1.x) + (a2.x + a3.x) + bias[2 * t];
    float h1 = (a0.y + a1.y) + (a2.y + a3.y) + bias[2 * t + 1];
    *(float2*)&g_h[(size_t)r * NH + 2 * t] =
        make_float2(fmaxf(h0, 0.f), fmaxf(h1, 0.f));
}

// ---------------------------------------------------------------------------
// GEMM2 (tf32 mma, 3-stage cp.async): g_hw = g_h[8192,512] @ [W1|W2][512,64].
// BM=32, BK=32, grid 256, 8 warps (2M x 4N), warp tile 16x16.
// ---------------------------------------------------------------------------
__global__ __launch_bounds__(256) void k_gemm2(const float* __restrict__ W1,
                                               const float* __restrict__ W2) {
    __shared__ float As[3][32][36];
    __shared__ float Bs[3][32][72];
    int tid = threadIdx.x, lane = tid & 31, wid = tid >> 5;
    int g = lane >> 2, t = lane & 3;
    int bm = blockIdx.x * 32;
    int wm = (wid & 1) * 16, wn = (wid >> 1) * 16;

    float acc[2][4];
#pragma unroll
    for (int ni = 0; ni < 2; ni++)
#pragma unroll
        for (int j = 0; j < 4; j++) acc[ni][j] = 0.f;

    int a_row = tid >> 3, a_c4 = (tid & 7) * 4;
    int b_row[2], b_c4[2];
#pragma unroll
    for (int l = 0; l < 2; l++) {
        int idx = tid * 2 + l;
        b_row[l] = idx >> 4;  b_c4[l] = (idx & 15) * 4;
    }

#pragma unroll
    for (int s = 0; s < 2; s++) {
        int k0 = s * 32;
        cpa16(&As[s][a_row][a_c4], &g_h[(size_t)(bm + a_row) * NH + k0 + a_c4]);
#pragma unroll
        for (int l = 0; l < 2; l++) {
            const float* src = (b_c4[l] < 32)
                ? &W1[(size_t)(k0 + b_row[l]) * NZ + b_c4[l]]
                : &W2[(size_t)(k0 + b_row[l]) * NZ + (b_c4[l] - 32)];
            cpa16(&Bs[s][b_row[l]][b_c4[l]], src);
        }
        cpa_commit();
    }

    const int NKT = NH / 32;   // 16
    for (int kt = 0; kt < NKT; kt++) {
        int st = kt % 3;
        if (kt == NKT - 1) asm volatile("cp.async.wait_group 0;");
        else               asm volatile("cp.async.wait_group 1;");
        __syncthreads();
        if (kt + 2 < NKT) {
            int ns = (kt + 2) % 3, k0 = (kt + 2) * 32;
            cpa16(&As[ns][a_row][a_c4], &g_h[(size_t)(bm + a_row) * NH + k0 + a_c4]);
#pragma unroll
            for (int l = 0; l < 2; l++) {
                const float* src = (b_c4[l] < 32)
                    ? &W1[(size_t)(k0 + b_row[l]) * NZ + b_c4[l]]
                    : &W2[(size_t)(k0 + b_row[l]) * NZ + (b_c4[l] - 32)];
                cpa16(&Bs[ns][b_row[l]][b_c4[l]], src);
            }
            cpa_commit();
        }
#pragma unroll
        for (int ks = 0; ks < 32; ks += 8) {
            unsigned af[4], bf[2][2];
            af[0] = f2tf(As[st][wm + g][ks + t]);
            af[1] = f2tf(As[st][wm + g + 8][ks + t]);
            af[2] = f2tf(As[st][wm + g][ks + t + 4]);
            af[3] = f2tf(As[st][wm + g + 8][ks + t + 4]);
#pragma unroll
            for (int ni = 0; ni < 2; ni++) {
                int n0 = wn + ni * 8;
                bf[ni][0] = f2tf(Bs[st][ks + t][n0 + g]);
                bf[ni][1] = f2tf(Bs[st][ks + t + 4][n0 + g]);
            }
#pragma unroll
            for (int ni = 0; ni < 2; ni++)
                mma_tf32(acc[ni], af, bf[ni]);
        }
    }
#pragma unroll
    for (int ni = 0; ni < 2; ni++) {
        int row = bm + wm + g;
        int col = wn + ni * 8 + 2 * t;
        *(float2*)&g_hw[(size_t)row * 64 + col] = make_float2(acc[ni][0], acc[ni][1]);
        *(float2*)&g_hw[(size_t)(row + 8) * 64 + col] = make_float2(acc[ni][2], acc[ni][3]);
    }
}

// ---------------------------------------------------------------------------
// SpMM2: mu/logvar = relu(spmm(g_hw) + bias); writes z/mu/logvar + g_z.
// ---------------------------------------------------------------------------
__global__ __launch_bounds__(256) void k_spmm2(const float* __restrict__ vals,
                                               const int* __restrict__ cols,
                                               const float* __restrict__ b1,
                                               const float* __restrict__ b2,
                                               float* __restrict__ out) {
    int tx = threadIdx.x;                        // 0..63
    int r = blockIdx.x * 4 + threadIdx.y;
    int s = g_rowptr[r], e = g_rowptr[r + 1];
    float a0 = 0, a1 = 0, a2 = 0, a3 = 0;
    int i = s;
    for (; i + 4 <= e; i += 4) {
        float v0 = vals[i], v1 = vals[i + 1], v2 = vals[i + 2], v3 = vals[i + 3];
        int   j0 = cols[i], j1 = cols[i + 1], j2 = cols[i + 2], j3 = cols[i + 3];
        a0 += v0 * g_hw[(size_t)j0 * 64 + tx];
        a1 += v1 * g_hw[(size_t)j1 * 64 + tx];
        a2 += v2 * g_hw[(size_t)j2 * 64 + tx];
        a3 += v3 * g_hw[(size_t)j3 * 64 + tx];
    }
    for (; i < e; i++) {
        a0 += vals[i] * g_hw[(size_t)cols[i] * 64 + tx];
    }
    float bias = (tx < 32) ? b1[tx] : b2[tx - 32];
    float v = fmaxf((a0 + a1) + (a2 + a3) + bias, 0.f);
    g_z[(size_t)r * 64 + tx] = v;

    size_t base = (size_t)NNODES * NNODES;       // after adj_recon
    if (tx < 32) {
        out[base + (size_t)r * NZ + tx] = v;                       // z
        out[base + (size_t)NNODES * NZ + (size_t)r * NZ + tx] = v; // mu
    } else {
        out[base + (size_t)NNODES * NZ * 2 + (size_t)r * NZ + (tx - 32)] = v; // logvar
    }
}

// ---------------------------------------------------------------------------
// Decoder (tf32 mma): adj_recon = sigmoid(z @ z^T). 128x128 tile, K=32.
// 8 warps (4M x 2N), warp tile 32x64. RNA fill; sigmoid via tanh.approx.
// ---------------------------------------------------------------------------
__global__ __launch_bounds__(256) void k_decoder(float* __restrict__ out) {
    __shared__ unsigned zA[32][136];
    __shared__ unsigned zB[32][136];
    int tid = threadIdx.x, lane = tid & 31, wid = tid >> 5;
    int g = lane >> 2, t = lane & 3;
    int i0 = blockIdx.y * 128, j0 = blockIdx.x * 128;
    int wm = (wid & 3) * 32, wn = (wid >> 2) * 64;

#pragma unroll
    for (int l = 0; l < 4; l++) {
        int idx = tid * 4 + l;
        int row = idx >> 3, c4 = (idx & 7) * 4;
        float4 va = *(const float4*)&g_z[(size_t)(i0 + row) * 64 + c4];
        zA[c4 + 0][row] = f2tf(va.x); zA[c4 + 1][row] = f2tf(va.y);
        zA[c4 + 2][row] = f2tf(va.z); zA[c4 + 3][row] = f2tf(va.w);
        float4 vb = *(const float4*)&g_z[(size_t)(j0 + row) * 64 + c4];
        zB[c4 + 0][row] = f2tf(vb.x); zB[c4 + 1][row] = f2tf(vb.y);
        zB[c4 + 2][row] = f2tf(vb.z); zB[c4 + 3][row] = f2tf(vb.w);
    }
    __syncthreads();

    float acc[2][8][4];
#pragma unroll
    for (int mi = 0; mi < 2; mi++)
#pragma unroll
        for (int ni = 0; ni < 8; ni++)
#pragma unroll
            for (int j = 0; j < 4; j++) acc[mi][ni][j] = 0.f;

#pragma unroll
    for (int ks = 0; ks < NZ; ks += 8) {
        unsigned af[2][4], bf[8][2];
#pragma unroll
        for (int mi = 0; mi < 2; mi++) {
            int m0 = wm + mi * 16;
            af[mi][0] = zA[ks + t][m0 + g];
            af[mi][1] = zA[ks + t][m0 + g + 8];
            af[mi][2] = zA[ks + t + 4][m0 + g];
            af[mi][3] = zA[ks + t + 4][m0 + g + 8];
        }
#pragma unroll
        for (int ni = 0; ni < 8; ni++) {
            int n0 = wn + ni * 8;
            bf[ni][0] = zB[ks + t][n0 + g];
            bf[ni][1] = zB[ks + t + 4][n0 + g];
        }
#pragma unroll
        for (int mi = 0; mi < 2; mi++)
#pragma unroll
            for (int ni = 0; ni < 8; ni++)
                mma_tf32(acc[mi][ni], af[mi], bf[ni]);
    }

#pragma unroll
    for (int mi = 0; mi < 2; mi++)
#pragma unroll
        for (int ni = 0; ni < 8; ni++) {
            int row = i0 + wm + mi * 16 + g;
            int col = j0 + wn + ni * 8 + 2 * t;
            float s0 = fast_sigmoid(acc[mi][ni][0]);
            float s1 = fast_sigmoid(acc[mi][ni][1]);
            float s2 = fast_sigmoid(acc[mi][ni][2]);
            float s3 = fast_sigmoid(acc[mi][ni][3]);
            *(float2*)&out[(size_t)row * NNODES + col]       = make_float2(s0, s1);
            *(float2*)&out[(size_t)(row + 8) * NNODES + col] = make_float2(s2, s3);
        }
}

// ---------------------------------------------------------------------------
extern "C" void kernel_launch(void* const* d_in, const int* in_sizes, int n_in,
                              void* d_out, int out_size) {
    const float* x    = (const float*)d_in[0];
    const float* vals = (const float*)d_in[1];
    const float* W0   = (const float*)d_in[2];
    const float* b0   = (const float*)d_in[3];
    const float* W1   = (const float*)d_in[4];
    const float* b1   = (const float*)d_in[5];
    const float* W2   = (const float*)d_in[6];
    const float* b2   = (const float*)d_in[7];
    const int*   rows = (const int*)d_in[8];
    const int*   cols = (const int*)d_in[9];
    int E = in_sizes[1];
    float* out = (float*)d_out;

    __nv_bfloat162* xb = nullptr;
    cudaGetSymbolAddress((void**)&xb, g_xb);

    const int GEMM1_SMEM = 3 * 2 * 128 * 40 * 2;   // 61440 B
    cudaFuncSetAttribute(k_gemm1, cudaFuncAttributeMaxDynamicSharedMemorySize,
                         GEMM1_SMEM);

    k_rowptr<<<(NNODES + 256) / 256, 256>>>(rows, E);
    k_cvt_bf16<<<(NNODES * NF / 4 + 255) / 256, 256>>>(x, xb, NNODES * NF / 4);
    k_cvt_w0t<<<dim3(NH / 32, NF / 32), dim3(32, 8)>>>(W0);
    k_gemm1<<<dim3(NH / 128, NNODES / 128), 512, GEMM1_SMEM>>>();
    k_spmm1<<<NNODES, 256>>>(vals, cols, b0);
    k_gemm2<<<NNODES / 32, 256>>>(W1, W2);
    k_spmm2<<<NNODES / 4, dim3(64, 4)>>>(vals, cols, b1, b2, out);
    k_decoder<<<dim3(NNODES / 128, NNODES / 128), 256>>>(out);
}

// round 10
// speedup vs baseline: 1.4819x; 1.1676x over previous
#include <cuda_runtime.h>
#include <cuda_bf16.h>

#define NNODES 8192
#define NF 1024
#define NH 512
#define NZ 32

// ---- scratch (device globals; no allocation allowed) ----
__device__ __nv_bfloat16 g_xb[NNODES * NF];        // x as bf16 [m][k]
__device__ __nv_bfloat16 g_w0t[NH * NF];           // W0^T as bf16 [n][k]
__device__ __nv_bfloat162 g_xw0h[NNODES * NH / 2]; // x @ W0 (bf16 pairs)
__device__ float g_h[NNODES * NH];                 // relu(spmm + b0) fp32
__device__ float g_hw[NNODES * 64];                // h @ [W1|W2] fp32
__device__ __nv_bfloat16 g_zh[NNODES * NZ];        // mu as bf16 (decoder input)
__device__ int   g_rowptr[NNODES + 1];

__device__ __forceinline__ unsigned f2tf(float f) {
    unsigned u;
    asm("cvt.rna.tf32.f32 %0, %1;" : "=r"(u) : "f"(f));
    return u;
}

__device__ __forceinline__ void mma_tf32(float c[4], const unsigned a[4],
                                         const unsigned b[2]) {
    asm volatile(
        "mma.sync.aligned.m16n8k8.row.col.f32.tf32.tf32.f32 "
        "{%0,%1,%2,%3}, {%4,%5,%6,%7}, {%8,%9}, {%0,%1,%2,%3};"
        : "+f"(c[0]), "+f"(c[1]), "+f"(c[2]), "+f"(c[3])
        : "r"(a[0]), "r"(a[1]), "r"(a[2]), "r"(a[3]), "r"(b[0]), "r"(b[1]));
}

__device__ __forceinline__ void mma_bf16(float c[4], const unsigned a[4],
                                         const unsigned b0, const unsigned b1) {
    asm volatile(
        "mma.sync.aligned.m16n8k16.row.col.f32.bf16.bf16.f32 "
        "{%0,%1,%2,%3}, {%4,%5,%6,%7}, {%8,%9}, {%0,%1,%2,%3};"
        : "+f"(c[0]), "+f"(c[1]), "+f"(c[2]), "+f"(c[3])
        : "r"(a[0]), "r"(a[1]), "r"(a[2]), "r"(a[3]), "r"(b0), "r"(b1));
}

__device__ __forceinline__ void ldsm_x4(unsigned& r0, unsigned& r1,
                                        unsigned& r2, unsigned& r3,
                                        const void* p) {
    unsigned sa = (unsigned)__cvta_generic_to_shared(p);
    asm volatile("ldmatrix.sync.aligned.m8n8.x4.shared.b16 {%0,%1,%2,%3}, [%4];"
                 : "=r"(r0), "=r"(r1), "=r"(r2), "=r"(r3) : "r"(sa));
}

__device__ __forceinline__ void cpa16(void* s, const void* g) {
    unsigned sa = (unsigned)__cvta_generic_to_shared(s);
    asm volatile("cp.async.cg.shared.global [%0], [%1], 16;" :: "r"(sa), "l"(g));
}
__device__ __forceinline__ void cpa_commit() {
    asm volatile("cp.async.commit_group;");
}

__device__ __forceinline__ float fast_sigmoid(float x) {
    float th;
    asm("tanh.approx.f32 %0, %1;" : "=f"(th) : "f"(0.5f * x));
    return fmaf(0.5f, th, 0.5f);
}

// ---------------------------------------------------------------------------
// CSR row pointers (binary search on sorted rows).
// ---------------------------------------------------------------------------
__global__ void k_rowptr(const int* __restrict__ rows, int E) {
    int r = blockIdx.x * blockDim.x + threadIdx.x;
    if (r > NNODES) return;
    int lo = 0, hi = E;
    while (lo < hi) {
        int mid = (lo + hi) >> 1;
        if (rows[mid] < r) lo = mid + 1; else hi = mid;
    }
    g_rowptr[r] = lo;
}

// ---------------------------------------------------------------------------
// Convert fp32 -> bf16 (RNE). n4 = element count / 4.
// ---------------------------------------------------------------------------
__global__ void k_cvt_bf16(const float* __restrict__ src,
                           __nv_bfloat162* __restrict__ dst, int n4) {
    int i = blockIdx.x * blockDim.x + threadIdx.x;
    if (i >= n4) return;
    float4 v = ((const float4*)src)[i];
    dst[i * 2 + 0] = __float22bfloat162_rn(make_float2(v.x, v.y));
    dst[i * 2 + 1] = __float22bfloat162_rn(make_float2(v.z, v.w));
}

// ---------------------------------------------------------------------------
// W0[1024,512] fp32 -> g_w0t[512,1024] bf16 (tiled transpose via smem).
// grid (NH/32, NF/32), block (32, 8).
// ---------------------------------------------------------------------------
__global__ void k_cvt_w0t(const float* __restrict__ W0) {
    __shared__ float tile[32][33];
    int n0 = blockIdx.x * 32, k0 = blockIdx.y * 32;
#pragma unroll
    for (int i = 0; i < 4; i++) {
        int k = threadIdx.y * 4 + i;           // 0..31
        tile[k][threadIdx.x] = W0[(size_t)(k0 + k) * NH + n0 + threadIdx.x];
    }
    __syncthreads();
#pragma unroll
    for (int i = 0; i < 4; i++) {
        int n = threadIdx.y * 4 + i;
        g_w0t[(size_t)(n0 + n) * NF + k0 + threadIdx.x] =
            __float2bfloat16_rn(tile[threadIdx.x][n]);
    }
}

// ---------------------------------------------------------------------------
// GEMM1 (bf16 mma m16n8k16 + ldmatrix, 3-stage cp.async, 512 thr):
// g_xw0h = xb[8192,1024] @ w0t^T -> bf16. BM=BN=128, BK=32.
// 16 warps (4M x 4N), warp tile 32x32, 1 sync per kt.
// As/Bs [row][k] bf16, stride 40 (per-LDSM-phase conflict-free).
// Dynamic smem: 3 * 2 * 128*40*2 = 61440 B.
// ---------------------------------------------------------------------------
__global__ __launch_bounds__(512, 2) void k_gemm1() {
    extern __shared__ unsigned short dsm[];
    unsigned short (*As)[128][40] = (unsigned short (*)[128][40])dsm;
    unsigned short (*Bs)[128][40] = (unsigned short (*)[128][40])(dsm + 3 * 128 * 40);

    int tid = threadIdx.x, lane = tid & 31, wid = tid >> 5;
    int g = lane >> 2, t = lane & 3;
    int bm = blockIdx.y * 128, bn = blockIdx.x * 128;
    int wm = (wid & 3) * 32, wn = (wid >> 2) * 32;
    int lrow = lane & 15, lkoff = (lane >> 4) * 8;   // ldmatrix lane addressing

    float acc[2][4][4];
#pragma unroll
    for (int mi = 0; mi < 2; mi++)
#pragma unroll
        for (int ni = 0; ni < 4; ni++)
#pragma unroll
            for (int j = 0; j < 4; j++) acc[mi][ni][j] = 0.f;

    int l_row = tid >> 2, l_c8 = (tid & 3) * 8;

#pragma unroll
    for (int s = 0; s < 2; s++) {
        int k0 = s * 32;
        cpa16(&As[s][l_row][l_c8], &g_xb[(size_t)(bm + l_row) * NF + k0 + l_c8]);
        cpa16(&Bs[s][l_row][l_c8], &g_w0t[(size_t)(bn + l_row) * NF + k0 + l_c8]);
        cpa_commit();
    }

    const int NKT = NF / 32;   // 32
    for (int kt = 0; kt < NKT; kt++) {
        int st = kt % 3;
        if (kt == NKT - 1) asm volatile("cp.async.wait_group 0;");
        else               asm volatile("cp.async.wait_group 1;");
        __syncthreads();
        if (kt + 2 < NKT) {
            int ns = (kt + 2) % 3, k0 = (kt + 2) * 32;
            cpa16(&As[ns][l_row][l_c8], &g_xb[(size_t)(bm + l_row) * NF + k0 + l_c8]);
            cpa16(&Bs[ns][l_row][l_c8], &g_w0t[(size_t)(bn + l_row) * NF + k0 + l_c8]);
            cpa_commit();
        }
#pragma unroll
        for (int ks = 0; ks < 32; ks += 16) {
            unsigned af[2][4], bq[2][4];
#pragma unroll
            for (int mi = 0; mi < 2; mi++)
                ldsm_x4(af[mi][0], af[mi][1], af[mi][2], af[mi][3],
                        &As[st][wm + mi * 16 + lrow][ks + lkoff]);
#pragma unroll
            for (int p = 0; p < 2; p++)
                ldsm_x4(bq[p][0], bq[p][1], bq[p][2], bq[p][3],
                        &Bs[st][wn + p * 16 + lrow][ks + lkoff]);
#pragma unroll
            for (int mi = 0; mi < 2; mi++)
#pragma unroll
                for (int p = 0; p < 2; p++) {
                    mma_bf16(acc[mi][2 * p],     af[mi], bq[p][0], bq[p][2]);
                    mma_bf16(acc[mi][2 * p + 1], af[mi], bq[p][1], bq[p][3]);
                }
        }
    }
#pragma unroll
    for (int mi = 0; mi < 2; mi++)
#pragma unroll
        for (int ni = 0; ni < 4; ni++) {
            int row = bm + wm + mi * 16 + g;
            int col = bn + wn + ni * 8 + 2 * t;
            g_xw0h[((size_t)row * NH + col) >> 1] =
                __float22bfloat162_rn(make_float2(acc[mi][ni][0], acc[mi][ni][1]));
            g_xw0h[((size_t)(row + 8) * NH + col) >> 1] =
                __float22bfloat162_rn(make_float2(acc[mi][ni][2], acc[mi][ni][3]));
        }
}

// ---------------------------------------------------------------------------
// SpMM1: g_h[r,:] = relu(sum vals*xw0[cols,:] + b0). bf16x2 gather, fp32 acc.
// ---------------------------------------------------------------------------
__global__ __launch_bounds__(256) void k_spmm1(const float* __restrict__ vals,
                                               const int* __restrict__ cols,
                                               const float* __restrict__ bias) {
    int r = blockIdx.x;
    int t = threadIdx.x;
    int s = g_rowptr[r], e = g_rowptr[r + 1];
    float2 a0 = {0, 0}, a1 = {0, 0}, a2 = {0, 0}, a3 = {0, 0};
    int i = s;
    for (; i + 4 <= e; i += 4) {
        float v0 = vals[i], v1 = vals[i + 1], v2 = vals[i + 2], v3 = vals[i + 3];
        int   j0 = cols[i], j1 = cols[i + 1], j2 = cols[i + 2], j3 = cols[i + 3];
        float2 f0 = __bfloat1622float2(g_xw0h[(size_t)j0 * 256 + t]);
        float2 f1 = __bfloat1622float2(g_xw0h[(size_t)j1 * 256 + t]);
        float2 f2 = __bfloat1622float2(g_xw0h[(size_t)j2 * 256 + t]);
        float2 f3 = __bfloat1622float2(g_xw0h[(size_t)j3 * 256 + t]);
        a0.x += v0 * f0.x; a0.y += v0 * f0.y;
        a1.x += v1 * f1.x; a1.y += v1 * f1.y;
        a2.x += v2 * f2.x; a2.y += v2 * f2.y;
        a3.x += v3 * f3.x; a3.y += v3 * f3.y;
    }
    for (; i < e; i++) {
        float v = vals[i];
        float2 f = __bfloat1622float2(g_xw0h[(size_t)cols[i] * 256 + t]);
        a0.x += v * f.x; a0.y += v * f.y;
    }
    float h0 = (a0.x + a1.x) + (a2.x + a3.x) + bias[2 * t];
    float h1 = (a0.y + a1.y) + (a2.y + a3.y) + bias[2 * t + 1];
    *(float2*)&g_h[(size_t)r * NH + 2 * t] =
        make_float2(fmaxf(h0, 0.f), fmaxf(h1, 0.f));
}

// ---------------------------------------------------------------------------
// GEMM2 (tf32 mma, 3-stage cp.async): g_hw = g_h[8192,512] @ [W1|W2][512,64].
// BM=32, BK=32, grid 256, 8 warps (2M x 4N), warp tile 16x16.
// ---------------------------------------------------------------------------
__global__ __launch_bounds__(256) void k_gemm2(const float* __restrict__ W1,
                                               const float* __restrict__ W2) {
    __shared__ float As[3][32][36];
    __shared__ float Bs[3][32][72];
    int tid = threadIdx.x, lane = tid & 31, wid = tid >> 5;
    int g = lane >> 2, t = lane & 3;
    int bm = blockIdx.x * 32;
    int wm = (wid & 1) * 16, wn = (wid >> 1) * 16;

    float acc[2][4];
#pragma unroll
    for (int ni = 0; ni < 2; ni++)
#pragma unroll
        for (int j = 0; j < 4; j++) acc[ni][j] = 0.f;

    int a_row = tid >> 3, a_c4 = (tid & 7) * 4;
    int b_row[2], b_c4[2];
#pragma unroll
    for (int l = 0; l < 2; l++) {
        int idx = tid * 2 + l;
        b_row[l] = idx >> 4;  b_c4[l] = (idx & 15) * 4;
    }

#pragma unroll
    for (int s = 0; s < 2; s++) {
        int k0 = s * 32;
        cpa16(&As[s][a_row][a_c4], &g_h[(size_t)(bm + a_row) * NH + k0 + a_c4]);
#pragma unroll
        for (int l = 0; l < 2; l++) {
            const float* src = (b_c4[l] < 32)
                ? &W1[(size_t)(k0 + b_row[l]) * NZ + b_c4[l]]
                : &W2[(size_t)(k0 + b_row[l]) * NZ + (b_c4[l] - 32)];
            cpa16(&Bs[s][b_row[l]][b_c4[l]], src);
        }
        cpa_commit();
    }

    const int NKT = NH / 32;   // 16
    for (int kt = 0; kt < NKT; kt++) {
        int st = kt % 3;
        if (kt == NKT - 1) asm volatile("cp.async.wait_group 0;");
        else               asm volatile("cp.async.wait_group 1;");
        __syncthreads();
        if (kt + 2 < NKT) {
            int ns = (kt + 2) % 3, k0 = (kt + 2) * 32;
            cpa16(&As[ns][a_row][a_c4], &g_h[(size_t)(bm + a_row) * NH + k0 + a_c4]);
#pragma unroll
            for (int l = 0; l < 2; l++) {
                const float* src = (b_c4[l] < 32)
                    ? &W1[(size_t)(k0 + b_row[l]) * NZ + b_c4[l]]
                    : &W2[(size_t)(k0 + b_row[l]) * NZ + (b_c4[l] - 32)];
                cpa16(&Bs[ns][b_row[l]][b_c4[l]], src);
            }
            cpa_commit();
        }
#pragma unroll
        for (int ks = 0; ks < 32; ks += 8) {
            unsigned af[4], bf[2][2];
            af[0] = f2tf(As[st][wm + g][ks + t]);
            af[1] = f2tf(As[st][wm + g + 8][ks + t]);
            af[2] = f2tf(As[st][wm + g][ks + t + 4]);
            af[3] = f2tf(As[st][wm + g + 8][ks + t + 4]);
#pragma unroll
            for (int ni = 0; ni < 2; ni++) {
                int n0 = wn + ni * 8;
                bf[ni][0] = f2tf(Bs[st][ks + t][n0 + g]);
                bf[ni][1] = f2tf(Bs[st][ks + t + 4][n0 + g]);
            }
#pragma unroll
            for (int ni = 0; ni < 2; ni++)
                mma_tf32(acc[ni], af, bf[ni]);
        }
    }
#pragma unroll
    for (int ni = 0; ni < 2; ni++) {
        int row = bm + wm + g;
        int col = wn + ni * 8 + 2 * t;
        *(float2*)&g_hw[(size_t)row * 64 + col] = make_float2(acc[ni][0], acc[ni][1]);
        *(float2*)&g_hw[(size_t)(row + 8) * 64 + col] = make_float2(acc[ni][2], acc[ni][3]);
    }
}

// ---------------------------------------------------------------------------
// SpMM2: mu/logvar = relu(spmm(g_hw) + bias); writes z/mu/logvar (fp32) to out
// and mu as bf16 to g_zh for the decoder.
// ---------------------------------------------------------------------------
__global__ __launch_bounds__(256) void k_spmm2(const float* __restrict__ vals,
                                               const int* __restrict__ cols,
                                               const float* __restrict__ b1,
                                               const float* __restrict__ b2,
                                               float* __restrict__ out) {
    int tx = threadIdx.x;                        // 0..63
    int r = blockIdx.x * 4 + threadIdx.y;
    int s = g_rowptr[r], e = g_rowptr[r + 1];
    float a0 = 0, a1 = 0, a2 = 0, a3 = 0;
    int i = s;
    for (; i + 4 <= e; i += 4) {
        float v0 = vals[i], v1 = vals[i + 1], v2 = vals[i + 2], v3 = vals[i + 3];
        int   j0 = cols[i], j1 = cols[i + 1], j2 = cols[i + 2], j3 = cols[i + 3];
        a0 += v0 * g_hw[(size_t)j0 * 64 + tx];
        a1 += v1 * g_hw[(size_t)j1 * 64 + tx];
        a2 += v2 * g_hw[(size_t)j2 * 64 + tx];
        a3 += v3 * g_hw[(size_t)j3 * 64 + tx];
    }
    for (; i < e; i++) {
        a0 += vals[i] * g_hw[(size_t)cols[i] * 64 + tx];
    }
    float bias = (tx < 32) ? b1[tx] : b2[tx - 32];
    float v = fmaxf((a0 + a1) + (a2 + a3) + bias, 0.f);

    size_t base = (size_t)NNODES * NNODES;       // after adj_recon
    if (tx < 32) {
        out[base + (size_t)r * NZ + tx] = v;                       // z
        out[base + (size_t)NNODES * NZ + (size_t)r * NZ + tx] = v; // mu
        g_zh[(size_t)r * NZ + tx] = __float2bfloat16_rn(v);        // decoder input
    } else {
        out[base + (size_t)NNODES * NZ * 2 + (size_t)r * NZ + (tx - 32)] = v; // logvar
    }
}

// ---------------------------------------------------------------------------
// Decoder (bf16 mma m16n8k16 + ldmatrix): adj_recon = sigmoid(z @ z^T).
// 128x128 tile, K=32 (2 k-steps). 8 warps (4M x 2N), warp tile 32x64.
// zA/zB [row][k] bf16 stride 40 (per-LDSM-phase conflict-free).
// ---------------------------------------------------------------------------
__global__ __launch_bounds__(256) void k_decoder(float* __restrict__ out) {
    __shared__ unsigned short zA[128][40];
    __shared__ unsigned short zB[128][40];
    int tid = threadIdx.x, lane = tid & 31, wid = tid >> 5;
    int g = lane >> 2, t = lane & 3;
    int i0 = blockIdx.y * 128, j0 = blockIdx.x * 128;
    int wm = (wid & 3) * 32, wn = (wid >> 2) * 64;
    int lrow = lane & 15, lkoff = (lane >> 4) * 8;

    // fill: each tile = 128 rows x 32 bf16 (64 B/row) = 512 x 16B, 2/thread
#pragma unroll
    for (int l = 0; l < 2; l++) {
        int idx = tid + l * 256;
        int row = idx >> 2, c8 = (idx & 3) * 8;
        *(uint4*)&zA[row][c8] = *(const uint4*)&g_zh[(size_t)(i0 + row) * NZ + c8];
        *(uint4*)&zB[row][c8] = *(const uint4*)&g_zh[(size_t)(j0 + row) * NZ + c8];
    }
    __syncthreads();

    float acc[2][8][4];
#pragma unroll
    for (int mi = 0; mi < 2; mi++)
#pragma unroll
        for (int ni = 0; ni < 8; ni++)
#pragma unroll
            for (int j = 0; j < 4; j++) acc[mi][ni][j] = 0.f;

#pragma unroll
    for (int ks = 0; ks < NZ; ks += 16) {
        unsigned af[2][4], bq[4][4];
#pragma unroll
        for (int mi = 0; mi < 2; mi++)
            ldsm_x4(af[mi][0], af[mi][1], af[mi][2], af[mi][3],
                    &zA[wm + mi * 16 + lrow][ks + lkoff]);
#pragma unroll
        for (int p = 0; p < 4; p++)
            ldsm_x4(bq[p][0], bq[p][1], bq[p][2], bq[p][3],
                    &zB[wn + p * 16 + lrow][ks + lkoff]);
#pragma unroll
        for (int mi = 0; mi < 2; mi++)
#pragma unroll
            for (int p = 0; p < 4; p++) {
                mma_bf16(acc[mi][2 * p],     af[mi], bq[p][0], bq[p][2]);
                mma_bf16(acc[mi][2 * p + 1], af[mi], bq[p][1], bq[p][3]);
            }
    }

#pragma unroll
    for (int mi = 0; mi < 2; mi++)
#pragma unroll
        for (int ni = 0; ni < 8; ni++) {
            int row = i0 + wm + mi * 16 + g;
            int col = j0 + wn + ni * 8 + 2 * t;
            float s0 = fast_sigmoid(acc[mi][ni][0]);
            float s1 = fast_sigmoid(acc[mi][ni][1]);
            float s2 = fast_sigmoid(acc[mi][ni][2]);
            float s3 = fast_sigmoid(acc[mi][ni][3]);
            *(float2*)&out[(size_t)row * NNODES + col]       = make_float2(s0, s1);
            *(float2*)&out[(size_t)(row + 8) * NNODES + col] = make_float2(s2, s3);
        }
}

// ---------------------------------------------------------------------------
extern "C" void kernel_launch(void* const* d_in, const int* in_sizes, int n_in,
                              void* d_out, int out_size) {
    const float* x    = (const float*)d_in[0];
    const float* vals = (const float*)d_in[1];
    const float* W0   = (const float*)d_in[2];
    const float* b0   = (const float*)d_in[3];
    const float* W1   = (const float*)d_in[4];
    const float* b1   = (const float*)d_in[5];
    const float* W2   = (const float*)d_in[6];
    const float* b2   = (const float*)d_in[7];
    const int*   rows = (const int*)d_in[8];
    const int*   cols = (const int*)d_in[9];
    int E = in_sizes[1];
    float* out = (float*)d_out;

    __nv_bfloat162* xb = nullptr;
    cudaGetSymbolAddress((void**)&xb, g_xb);

    const int GEMM1_SMEM = 3 * 2 * 128 * 40 * 2;   // 61440 B
    cudaFuncSetAttribute(k_gemm1, cudaFuncAttributeMaxDynamicSharedMemorySize,
                         GEMM1_SMEM);

    k_rowptr<<<(NNODES + 256) / 256, 256>>>(rows, E);
    k_cvt_bf16<<<(NNODES * NF / 4 + 255) / 256, 256>>>(x, xb, NNODES * NF / 4);
    k_cvt_w0t<<<dim3(NH / 32, NF / 32), dim3(32, 8)>>>(W0);
    k_gemm1<<<dim3(NH / 128, NNODES / 128), 512, GEMM1_SMEM>>>();
    k_spmm1<<<NNODES, 256>>>(vals, cols, b0);
    k_gemm2<<<NNODES / 32, 256>>>(W1, W2);
    k_spmm2<<<NNODES / 4, dim3(64, 4)>>>(vals, cols, b1, b2, out);
    k_decoder<<<dim3(NNODES / 128, NNODES / 128), 256>>>(out);
}

// round 11
// speedup vs baseline: 1.5828x; 1.0680x over previous
#include <cuda_runtime.h>
#include <cuda_bf16.h>

#define NNODES 8192
#define NF 1024
#define NH 512
#define NZ 32

// ---- scratch (device globals; no allocation allowed) ----
__device__ __nv_bfloat16 g_xb[NNODES * NF];        // x as bf16 [m][k]
__device__ __nv_bfloat16 g_w0t[NH * NF];           // W0^T as bf16 [n][k]
__device__ __nv_bfloat16 g_w12t[64 * NH];          // [W1|W2]^T as bf16 [n][k]
__device__ __nv_bfloat162 g_xw0h[NNODES * NH / 2]; // x @ W0 (bf16 pairs)
__device__ __nv_bfloat162 g_hb[NNODES * NH / 2];   // relu(spmm+b0) bf16 pairs
__device__ float g_hw[NNODES * 64];                // h @ [W1|W2] fp32
__device__ __nv_bfloat16 g_zh[NNODES * NZ];        // mu as bf16 (decoder input)
__device__ int   g_rowptr[NNODES + 1];

__device__ __forceinline__ void mma_bf16(float c[4], const unsigned a[4],
                                         const unsigned b0, const unsigned b1) {
    asm volatile(
        "mma.sync.aligned.m16n8k16.row.col.f32.bf16.bf16.f32 "
        "{%0,%1,%2,%3}, {%4,%5,%6,%7}, {%8,%9}, {%0,%1,%2,%3};"
        : "+f"(c[0]), "+f"(c[1]), "+f"(c[2]), "+f"(c[3])
        : "r"(a[0]), "r"(a[1]), "r"(a[2]), "r"(a[3]), "r"(b0), "r"(b1));
}

__device__ __forceinline__ void ldsm_x4(unsigned& r0, unsigned& r1,
                                        unsigned& r2, unsigned& r3,
                                        const void* p) {
    unsigned sa = (unsigned)__cvta_generic_to_shared(p);
    asm volatile("ldmatrix.sync.aligned.m8n8.x4.shared.b16 {%0,%1,%2,%3}, [%4];"
                 : "=r"(r0), "=r"(r1), "=r"(r2), "=r"(r3) : "r"(sa));
}

__device__ __forceinline__ void cpa16(void* s, const void* g) {
    unsigned sa = (unsigned)__cvta_generic_to_shared(s);
    asm volatile("cp.async.cg.shared.global [%0], [%1], 16;" :: "r"(sa), "l"(g));
}
__device__ __forceinline__ void cpa_commit() {
    asm volatile("cp.async.commit_group;");
}

__device__ __forceinline__ float fast_sigmoid(float x) {
    float th;
    asm("tanh.approx.f32 %0, %1;" : "=f"(th) : "f"(0.5f * x));
    return fmaf(0.5f, th, 0.5f);
}

// ---------------------------------------------------------------------------
// Fused prep: [0,8192) cvt x->bf16 ; [8192,8225) rowptr ;
// [8225,8737) W0^T tiles ; [8737,8865) [W1|W2]^T.
// ---------------------------------------------------------------------------
#define PREP_CVT_BLKS   (NNODES * NF / 4 / 256)          // 8192
#define PREP_ROW_BLKS   33
#define PREP_W0T_BLKS   ((NH / 32) * (NF / 32))          // 512
#define PREP_W12_BLKS   (64 * NH / 256)                  // 128
#define PREP_BLKS (PREP_CVT_BLKS + PREP_ROW_BLKS + PREP_W0T_BLKS + PREP_W12_BLKS)

__global__ __launch_bounds__(256) void k_prep(const float* __restrict__ x,
                                              const float* __restrict__ W0,
                                              const float* __restrict__ W1,
                                              const float* __restrict__ W2,
                                              const int* __restrict__ rows, int E) {
    __shared__ float tile[32][33];
    int b = blockIdx.x, tid = threadIdx.x;
    if (b < PREP_CVT_BLKS) {                      // x -> bf16
        int i = b * 256 + tid;                    // float4 index
        float4 v = ((const float4*)x)[i];
        __nv_bfloat162* dst = (__nv_bfloat162*)g_xb;
        dst[i * 2 + 0] = __float22bfloat162_rn(make_float2(v.x, v.y));
        dst[i * 2 + 1] = __float22bfloat162_rn(make_float2(v.z, v.w));
    } else if (b < PREP_CVT_BLKS + PREP_ROW_BLKS) {   // rowptr
        int r = (b - PREP_CVT_BLKS) * 256 + tid;
        if (r > NNODES) return;
        int lo = 0, hi = E;
        while (lo < hi) {
            int mid = (lo + hi) >> 1;
            if (rows[mid] < r) lo = mid + 1; else hi = mid;
        }
        g_rowptr[r] = lo;
    } else if (b < PREP_CVT_BLKS + PREP_ROW_BLKS + PREP_W0T_BLKS) {  // W0^T
        int tb = b - PREP_CVT_BLKS - PREP_ROW_BLKS;
        int n0 = (tb & 15) * 32, k0 = (tb >> 4) * 32;
        int col = tid & 31, rr = tid >> 5;        // 8 rows per pass
#pragma unroll
        for (int i = 0; i < 4; i++)
            tile[rr + 8 * i][col] = W0[(size_t)(k0 + rr + 8 * i) * NH + n0 + col];
        __syncthreads();
#pragma unroll
        for (int i = 0; i < 4; i++) {
            int n = rr + 8 * i;
            g_w0t[(size_t)(n0 + n) * NF + k0 + col] =
                __float2bfloat16_rn(tile[col][n]);
        }
    } else {                                      // [W1|W2]^T
        int idx = (b - PREP_CVT_BLKS - PREP_ROW_BLKS - PREP_W0T_BLKS) * 256 + tid;
        int n = idx >> 9, k = idx & 511;
        float v = (n < 32) ? W1[(size_t)k * NZ + n] : W2[(size_t)k * NZ + (n - 32)];
        g_w12t[(size_t)n * NH + k] = __float2bfloat16_rn(v);
    }
}

// ---------------------------------------------------------------------------
// GEMM1 (bf16 mma m16n8k16 + ldmatrix, 3-stage cp.async, 512 thr):
// g_xw0h = xb[8192,1024] @ w0t^T -> bf16. BM=BN=128, BK=32.
// 16 warps (4M x 4N), warp tile 32x32, 1 sync per kt.
// ---------------------------------------------------------------------------
__global__ __launch_bounds__(512, 2) void k_gemm1() {
    extern __shared__ unsigned short dsm[];
    unsigned short (*As)[128][40] = (unsigned short (*)[128][40])dsm;
    unsigned short (*Bs)[128][40] = (unsigned short (*)[128][40])(dsm + 3 * 128 * 40);

    int tid = threadIdx.x, lane = tid & 31, wid = tid >> 5;
    int g = lane >> 2, t = lane & 3;
    int bm = blockIdx.y * 128, bn = blockIdx.x * 128;
    int wm = (wid & 3) * 32, wn = (wid >> 2) * 32;
    int lrow = lane & 15, lkoff = (lane >> 4) * 8;

    float acc[2][4][4];
#pragma unroll
    for (int mi = 0; mi < 2; mi++)
#pragma unroll
        for (int ni = 0; ni < 4; ni++)
#pragma unroll
            for (int j = 0; j < 4; j++) acc[mi][ni][j] = 0.f;

    int l_row = tid >> 2, l_c8 = (tid & 3) * 8;

#pragma unroll
    for (int s = 0; s < 2; s++) {
        int k0 = s * 32;
        cpa16(&As[s][l_row][l_c8], &g_xb[(size_t)(bm + l_row) * NF + k0 + l_c8]);
        cpa16(&Bs[s][l_row][l_c8], &g_w0t[(size_t)(bn + l_row) * NF + k0 + l_c8]);
        cpa_commit();
    }

    const int NKT = NF / 32;   // 32
    for (int kt = 0; kt < NKT; kt++) {
        int st = kt % 3;
        if (kt == NKT - 1) asm volatile("cp.async.wait_group 0;");
        else               asm volatile("cp.async.wait_group 1;");
        __syncthreads();
        if (kt + 2 < NKT) {
            int ns = (kt + 2) % 3, k0 = (kt + 2) * 32;
            cpa16(&As[ns][l_row][l_c8], &g_xb[(size_t)(bm + l_row) * NF + k0 + l_c8]);
            cpa16(&Bs[ns][l_row][l_c8], &g_w0t[(size_t)(bn + l_row) * NF + k0 + l_c8]);
            cpa_commit();
        }
#pragma unroll
        for (int ks = 0; ks < 32; ks += 16) {
            unsigned af[2][4], bq[2][4];
#pragma unroll
            for (int mi = 0; mi < 2; mi++)
                ldsm_x4(af[mi][0], af[mi][1], af[mi][2], af[mi][3],
                        &As[st][wm + mi * 16 + lrow][ks + lkoff]);
#pragma unroll
            for (int p = 0; p < 2; p++)
                ldsm_x4(bq[p][0], bq[p][1], bq[p][2], bq[p][3],
                        &Bs[st][wn + p * 16 + lrow][ks + lkoff]);
#pragma unroll
            for (int mi = 0; mi < 2; mi++)
#pragma unroll
                for (int p = 0; p < 2; p++) {
                    mma_bf16(acc[mi][2 * p],     af[mi], bq[p][0], bq[p][2]);
                    mma_bf16(acc[mi][2 * p + 1], af[mi], bq[p][1], bq[p][3]);
                }
        }
    }
#pragma unroll
    for (int mi = 0; mi < 2; mi++)
#pragma unroll
        for (int ni = 0; ni < 4; ni++) {
            int row = bm + wm + mi * 16 + g;
            int col = bn + wn + ni * 8 + 2 * t;
            g_xw0h[((size_t)row * NH + col) >> 1] =
                __float22bfloat162_rn(make_float2(acc[mi][ni][0], acc[mi][ni][1]));
            g_xw0h[((size_t)(row + 8) * NH + col) >> 1] =
                __float22bfloat162_rn(make_float2(acc[mi][ni][2], acc[mi][ni][3]));
        }
}

// ---------------------------------------------------------------------------
// SpMM1: h[r,:] = relu(sum vals*xw0[cols,:] + b0). bf16x2 gather, fp32 acc,
// bf16x2 store to g_hb.
// ---------------------------------------------------------------------------
__global__ __launch_bounds__(256) void k_spmm1(const float* __restrict__ vals,
                                               const int* __restrict__ cols,
                                               const float* __restrict__ bias) {
    int r = blockIdx.x;
    int t = threadIdx.x;
    int s = g_rowptr[r], e = g_rowptr[r + 1];
    float2 a0 = {0, 0}, a1 = {0, 0}, a2 = {0, 0}, a3 = {0, 0};
    int i = s;
    for (; i + 4 <= e; i += 4) {
        float v0 = vals[i], v1 = vals[i + 1], v2 = vals[i + 2], v3 = vals[i + 3];
        int   j0 = cols[i], j1 = cols[i + 1], j2 = cols[i + 2], j3 = cols[i + 3];
        float2 f0 = __bfloat1622float2(g_xw0h[(size_t)j0 * 256 + t]);
        float2 f1 = __bfloat1622float2(g_xw0h[(size_t)j1 * 256 + t]);
        float2 f2 = __bfloat1622float2(g_xw0h[(size_t)j2 * 256 + t]);
        float2 f3 = __bfloat1622float2(g_xw0h[(size_t)j3 * 256 + t]);
        a0.x += v0 * f0.x; a0.y += v0 * f0.y;
        a1.x += v1 * f1.x; a1.y += v1 * f1.y;
        a2.x += v2 * f2.x; a2.y += v2 * f2.y;
        a3.x += v3 * f3.x; a3.y += v3 * f3.y;
    }
    for (; i < e; i++) {
        float v = vals[i];
        float2 f = __bfloat1622float2(g_xw0h[(size_t)cols[i] * 256 + t]);
        a0.x += v * f.x; a0.y += v * f.y;
    }
    float h0 = (a0.x + a1.x) + (a2.x + a3.x) + bias[2 * t];
    float h1 = (a0.y + a1.y) + (a2.y + a3.y) + bias[2 * t + 1];
    g_hb[(size_t)r * 256 + t] =
        __float22bfloat162_rn(make_float2(fmaxf(h0, 0.f), fmaxf(h1, 0.f)));
}

// ---------------------------------------------------------------------------
// GEMM2 (bf16 mma + ldmatrix, 2-stage cp.async):
// g_hw = hb[8192,512] @ w12t^T[512,64]. BM=32, BN=64, BK=64, grid 256.
// 8 warps (2M x 4N), warp tile 16x16. Stride 72 shorts (conflict-free LDSM).
// ---------------------------------------------------------------------------
__global__ __launch_bounds__(256) void k_gemm2() {
    __shared__ unsigned short As[2][32][72];
    __shared__ unsigned short Bs[2][64][72];
    int tid = threadIdx.x, lane = tid & 31, wid = tid >> 5;
    int g = lane >> 2, t = lane & 3;
    int bm = blockIdx.x * 32;
    int wm = (wid & 1) * 16, wn = (wid >> 1) * 16;
    int lrow = lane & 15, lkoff = (lane >> 4) * 8;

    float acc[2][4];
#pragma unroll
    for (int ni = 0; ni < 2; ni++)
#pragma unroll
        for (int j = 0; j < 4; j++) acc[ni][j] = 0.f;

    const __nv_bfloat16* hb = (const __nv_bfloat16*)g_hb;
    // A: 32x64 bf16 = 256 chunks (1/thread); B: 64x64 = 512 chunks (2/thread)
    int a_row = tid >> 3, a_c8 = (tid & 7) * 8;
    int b_row[2], b_c8[2];
#pragma unroll
    for (int l = 0; l < 2; l++) {
        int idx = tid * 2 + l;
        b_row[l] = idx >> 3;  b_c8[l] = (idx & 7) * 8;
    }

    {   // prologue: stage 0
        cpa16(&As[0][a_row][a_c8], &hb[(size_t)(bm + a_row) * NH + a_c8]);
#pragma unroll
        for (int l = 0; l < 2; l++)
            cpa16(&Bs[0][b_row[l]][b_c8[l]], &g_w12t[(size_t)b_row[l] * NH + b_c8[l]]);
        cpa_commit();
    }

    const int NKT = NH / 64;   // 8
    for (int kt = 0; kt < NKT; kt++) {
        int st = kt & 1;
        if (kt + 1 < NKT) {
            int ns = st ^ 1, k0 = (kt + 1) * 64;
            cpa16(&As[ns][a_row][a_c8], &hb[(size_t)(bm + a_row) * NH + k0 + a_c8]);
#pragma unroll
            for (int l = 0; l < 2; l++)
                cpa16(&Bs[ns][b_row[l]][b_c8[l]],
                      &g_w12t[(size_t)b_row[l] * NH + k0 + b_c8[l]]);
            cpa_commit();
            asm volatile("cp.async.wait_group 1;");
        } else {
            asm volatile("cp.async.wait_group 0;");
        }
        __syncthreads();
#pragma unroll
        for (int ks = 0; ks < 64; ks += 16) {
            unsigned af[4], bq[4];
            ldsm_x4(af[0], af[1], af[2], af[3], &As[st][wm + lrow][ks + lkoff]);
            ldsm_x4(bq[0], bq[1], bq[2], bq[3], &Bs[st][wn + lrow][ks + lkoff]);
            mma_bf16(acc[0], af, bq[0], bq[2]);
            mma_bf16(acc[1], af, bq[1], bq[3]);
        }
        __syncthreads();
    }
#pragma unroll
    for (int ni = 0; ni < 2; ni++) {
        int row = bm + wm + g;
        int col = wn + ni * 8 + 2 * t;
        *(float2*)&g_hw[(size_t)row * 64 + col] = make_float2(acc[ni][0], acc[ni][1]);
        *(float2*)&g_hw[(size_t)(row + 8) * 64 + col] = make_float2(acc[ni][2], acc[ni][3]);
    }
}

// ---------------------------------------------------------------------------
// SpMM2: mu/logvar = relu(spmm(g_hw) + bias); writes z/mu/logvar (fp32) to out
// and mu as bf16 to g_zh for the decoder.
// ---------------------------------------------------------------------------
__global__ __launch_bounds__(256) void k_spmm2(const float* __restrict__ vals,
                                               const int* __restrict__ cols,
                                               const float* __restrict__ b1,
                                               const float* __restrict__ b2,
                                               float* __restrict__ out) {
    int tx = threadIdx.x;                        // 0..63
    int r = blockIdx.x * 4 + threadIdx.y;
    int s = g_rowptr[r], e = g_rowptr[r + 1];
    float a0 = 0, a1 = 0, a2 = 0, a3 = 0;
    int i = s;
    for (; i + 4 <= e; i += 4) {
        float v0 = vals[i], v1 = vals[i + 1], v2 = vals[i + 2], v3 = vals[i + 3];
        int   j0 = cols[i], j1 = cols[i + 1], j2 = cols[i + 2], j3 = cols[i + 3];
        a0 += v0 * g_hw[(size_t)j0 * 64 + tx];
        a1 += v1 * g_hw[(size_t)j1 * 64 + tx];
        a2 += v2 * g_hw[(size_t)j2 * 64 + tx];
        a3 += v3 * g_hw[(size_t)j3 * 64 + tx];
    }
    for (; i < e; i++) {
        a0 += vals[i] * g_hw[(size_t)cols[i] * 64 + tx];
    }
    float bias = (tx < 32) ? b1[tx] : b2[tx - 32];
    float v = fmaxf((a0 + a1) + (a2 + a3) + bias, 0.f);

    size_t base = (size_t)NNODES * NNODES;       // after adj_recon
    if (tx < 32) {
        out[base + (size_t)r * NZ + tx] = v;                       // z
        out[base + (size_t)NNODES * NZ + (size_t)r * NZ + tx] = v; // mu
        g_zh[(size_t)r * NZ + tx] = __float2bfloat16_rn(v);        // decoder input
    } else {
        out[base + (size_t)NNODES * NZ * 2 + (size_t)r * NZ + (tx - 32)] = v; // logvar
    }
}

// ---------------------------------------------------------------------------
// Decoder (bf16 mma m16n8k16 + ldmatrix): adj_recon = sigmoid(z @ z^T).
// 128x128 tile, K=32 (2 k-steps). 8 warps (4M x 2N), warp tile 32x64.
// ---------------------------------------------------------------------------
__global__ __launch_bounds__(256) void k_decoder(float* __restrict__ out) {
    __shared__ unsigned short zA[128][40];
    __shared__ unsigned short zB[128][40];
    int tid = threadIdx.x, lane = tid & 31, wid = tid >> 5;
    int g = lane >> 2, t = lane & 3;
    int i0 = blockIdx.y * 128, j0 = blockIdx.x * 128;
    int wm = (wid & 3) * 32, wn = (wid >> 2) * 64;
    int lrow = lane & 15, lkoff = (lane >> 4) * 8;

#pragma unroll
    for (int l = 0; l < 2; l++) {
        int idx = tid + l * 256;
        int row = idx >> 2, c8 = (idx & 3) * 8;
        *(uint4*)&zA[row][c8] = *(const uint4*)&g_zh[(size_t)(i0 + row) * NZ + c8];
        *(uint4*)&zB[row][c8] = *(const uint4*)&g_zh[(size_t)(j0 + row) * NZ + c8];
    }
    __syncthreads();

    float acc[2][8][4];
#pragma unroll
    for (int mi = 0; mi < 2; mi++)
#pragma unroll
        for (int ni = 0; ni < 8; ni++)
#pragma unroll
            for (int j = 0; j < 4; j++) acc[mi][ni][j] = 0.f;

#pragma unroll
    for (int ks = 0; ks < NZ; ks += 16) {
        unsigned af[2][4], bq[4][4];
#pragma unroll
        for (int mi = 0; mi < 2; mi++)
            ldsm_x4(af[mi][0], af[mi][1], af[mi][2], af[mi][3],
                    &zA[wm + mi * 16 + lrow][ks + lkoff]);
#pragma unroll
        for (int p = 0; p < 4; p++)
            ldsm_x4(bq[p][0], bq[p][1], bq[p][2], bq[p][3],
                    &zB[wn + p * 16 + lrow][ks + lkoff]);
#pragma unroll
        for (int mi = 0; mi < 2; mi++)
#pragma unroll
            for (int p = 0; p < 4; p++) {
                mma_bf16(acc[mi][2 * p],     af[mi], bq[p][0], bq[p][2]);
                mma_bf16(acc[mi][2 * p + 1], af[mi], bq[p][1], bq[p][3]);
            }
    }

#pragma unroll
    for (int mi = 0; mi < 2; mi++)
#pragma unroll
        for (int ni = 0; ni < 8; ni++) {
            int row = i0 + wm + mi * 16 + g;
            int col = j0 + wn + ni * 8 + 2 * t;
            float s0 = fast_sigmoid(acc[mi][ni][0]);
            float s1 = fast_sigmoid(acc[mi][ni][1]);
            float s2 = fast_sigmoid(acc[mi][ni][2]);
            float s3 = fast_sigmoid(acc[mi][ni][3]);
            *(float2*)&out[(size_t)row * NNODES + col]       = make_float2(s0, s1);
            *(float2*)&out[(size_t)(row + 8) * NNODES + col] = make_float2(s2, s3);
        }
}

// ---------------------------------------------------------------------------
extern "C" void kernel_launch(void* const* d_in, const int* in_sizes, int n_in,
                              void* d_out, int out_size) {
    const float* x    = (const float*)d_in[0];
    const float* vals = (const float*)d_in[1];
    const float* W0   = (const float*)d_in[2];
    const float* b0   = (const float*)d_in[3];
    const float* W1   = (const float*)d_in[4];
    const float* b1   = (const float*)d_in[5];
    const float* W2   = (const float*)d_in[6];
    const float* b2   = (const float*)d_in[7];
    const int*   rows = (const int*)d_in[8];
    const int*   cols = (const int*)d_in[9];
    int E = in_sizes[1];
    float* out = (float*)d_out;

    const int GEMM1_SMEM = 3 * 2 * 128 * 40 * 2;   // 61440 B
    cudaFuncSetAttribute(k_gemm1, cudaFuncAttributeMaxDynamicSharedMemorySize,
                         GEMM1_SMEM);

    k_prep<<<PREP_BLKS, 256>>>(x, W0, W1, W2, rows, E);
    k_gemm1<<<dim3(NH / 128, NNODES / 128), 512, GEMM1_SMEM>>>();
    k_spmm1<<<NNODES, 256>>>(vals, cols, b0);
    k_gemm2<<<NNODES / 32, 256>>>();
    k_spmm2<<<NNODES / 4, dim3(64, 4)>>>(vals, cols, b1, b2, out);
    k_decoder<<<dim3(NNODES / 128, NNODES / 128), 256>>>(out);
}